// round 3
// baseline (speedup 1.0000x reference)
#include <cuda_runtime.h>

#define N_NODES  40000
#define N_EDGES  640000
#define N_GRAPHS 256

// ---------------- scratch (static __device__, no allocation) ----------------
__device__ __align__(16) float g_deg[N_NODES];
__device__ __align__(16) float g_dis[N_NODES];
__device__ __align__(16) float g_h1[N_NODES * 128];
__device__ __align__(16) float g_agg1[N_NODES * 128];
__device__ __align__(16) float g_h2[N_NODES * 64];
__device__ __align__(16) float g_agg2[N_NODES * 64];
__device__ __align__(16) float g_h3[N_NODES * 32];
__device__ __align__(16) float g_agg3[N_NODES * 32];
__device__ __align__(16) float g_pooled[N_GRAPHS * 32];
__device__ __align__(16) float g_cnt[N_GRAPHS];

// vectorized global reduction (PTX ISA 8.1+, sm_90+)
__device__ __forceinline__ void red_add_v4(float* addr, float4 v) {
    asm volatile("red.global.add.v4.f32 [%0], {%1, %2, %3, %4};"
                 :: "l"(addr), "f"(v.x), "f"(v.y), "f"(v.z), "f"(v.w)
                 : "memory");
}

// ---------------- small prep kernels ----------------
__global__ void k_zero() {
    int i = blockIdx.x * blockDim.x + threadIdx.x;
    if (i < N_NODES) g_deg[i] = 0.f;
    if (i < N_GRAPHS * 32) g_pooled[i] = 0.f;
    if (i < N_GRAPHS) g_cnt[i] = 0.f;
}

__global__ void k_degree(const int* __restrict__ ei) {
    int e = blockIdx.x * blockDim.x + threadIdx.x;
    if (e < N_EDGES) {
        int d = ei[N_EDGES + e];
        atomicAdd(&g_deg[d], 1.0f);
    }
}

__global__ void k_dis() {
    int i = blockIdx.x * blockDim.x + threadIdx.x;
    if (i < N_NODES) g_dis[i] = rsqrtf(g_deg[i] + 1.0f);
}

// ---------------- fused node GEMM ----------------
// out_h = out_agg = (transform(in) @ W) * dis[row]
// transform(v) at feature k of row r: TRANSFORM ? relu(v*dis[r] + tb[k]) : v
template<int K, int N, bool TRANSFORM>
__global__ void k_gemm(const float* __restrict__ in, const float* __restrict__ W,
                       const float* __restrict__ tb,
                       float* __restrict__ out_h, float* __restrict__ out_agg) {
    constexpr int MT = 64;          // rows per block (40000 % 64 == 0 -> 625 blocks)
    constexpr int CT = N / 4;       // column-threads (each owns 4 contiguous cols)
    constexpr int RT = 256 / CT;    // row-threads
    constexpr int RM = MT / RT;     // rows per thread
    constexpr int KP = K + 4;       // padded X stride (bank-conflict avoidance)

    extern __shared__ float smem[];
    float* Ws = smem;               // K*N
    float* Xs = smem + K * N;       // MT*KP

    int tid  = threadIdx.x;
    int row0 = blockIdx.x * MT;

    // load W into smem
    #pragma unroll 4
    for (int i = tid; i < K * N / 4; i += 256)
        ((float4*)Ws)[i] = ((const float4*)W)[i];

    // load + transform X tile into smem (padded rows)
    for (int i = tid; i < MT * K / 4; i += 256) {
        int lin = i * 4;
        int r = lin / K;
        int k = lin - r * K;
        float4 v = ((const float4*)in)[(size_t)row0 * (K / 4) + i];
        if (TRANSFORM) {
            float dr = g_dis[row0 + r];
            v.x = fmaxf(fmaf(v.x, dr, tb[k + 0]), 0.f);
            v.y = fmaxf(fmaf(v.y, dr, tb[k + 1]), 0.f);
            v.z = fmaxf(fmaf(v.z, dr, tb[k + 2]), 0.f);
            v.w = fmaxf(fmaf(v.w, dr, tb[k + 3]), 0.f);
        }
        *(float4*)(Xs + r * KP + k) = v;
    }
    __syncthreads();

    int ct = tid % CT;
    int rt = tid / CT;

    float acc[RM][4];
    #pragma unroll
    for (int r = 0; r < RM; r++)
        acc[r][0] = acc[r][1] = acc[r][2] = acc[r][3] = 0.f;

    #pragma unroll 4
    for (int k = 0; k < K; k++) {
        float4 w = ((const float4*)Ws)[k * CT + ct];
        #pragma unroll
        for (int r = 0; r < RM; r++) {
            float xv = Xs[(rt + r * RT) * KP + k];
            acc[r][0] = fmaf(xv, w.x, acc[r][0]);
            acc[r][1] = fmaf(xv, w.y, acc[r][1]);
            acc[r][2] = fmaf(xv, w.z, acc[r][2]);
            acc[r][3] = fmaf(xv, w.w, acc[r][3]);
        }
    }

    #pragma unroll
    for (int r = 0; r < RM; r++) {
        int row = row0 + rt + r * RT;
        float dr = g_dis[row];
        float4 o = make_float4(acc[r][0] * dr, acc[r][1] * dr,
                               acc[r][2] * dr, acc[r][3] * dr);
        ((float4*)(out_h   + (size_t)row * N))[ct] = o;
        ((float4*)(out_agg + (size_t)row * N))[ct] = o;
    }
}

// ---------------- edge scatter: agg[dst] += h[src] ----------------
template<int F>   // features per node: 128 / 64 / 32
__global__ void k_scatter(const int* __restrict__ ei,
                          const float* __restrict__ h, float* __restrict__ agg) {
    constexpr int LPE = F / 4;       // lanes per edge
    constexpr int EPW = 32 / LPE;    // edges per warp
    int gw   = (blockIdx.x * blockDim.x + threadIdx.x) >> 5;
    int lane = threadIdx.x & 31;
    int sub  = lane / LPE;
    int l    = lane % LPE;
    int e = gw * EPW + sub;
    if (e >= N_EDGES) return;
    int s = ei[e];
    int d = ei[N_EDGES + e];
    float4 v = *(const float4*)(h + (size_t)s * F + l * 4);
    red_add_v4(agg + (size_t)d * F + l * 4, v);
}

// ---------------- final node transform + mean-pool accumulate ----------------
__global__ void k_pool(const int* __restrict__ batch,
                       const float* __restrict__ b3) {
    int gw   = (blockIdx.x * blockDim.x + threadIdx.x) >> 5;
    int lane = threadIdx.x & 31;
    int sub  = lane >> 3;            // 4 nodes per warp, 8 lanes each
    int l    = lane & 7;
    int node = gw * 4 + sub;
    if (node >= N_NODES) return;
    int g = batch[node];
    float dr = g_dis[node];
    float4 v = *(const float4*)(g_agg3 + (size_t)node * 32 + l * 4);
    v.x = fmaxf(fmaf(v.x, dr, b3[l * 4 + 0]), 0.f);
    v.y = fmaxf(fmaf(v.y, dr, b3[l * 4 + 1]), 0.f);
    v.z = fmaxf(fmaf(v.z, dr, b3[l * 4 + 2]), 0.f);
    v.w = fmaxf(fmaf(v.w, dr, b3[l * 4 + 3]), 0.f);
    red_add_v4(g_pooled + g * 32 + l * 4, v);
    if (l == 0) atomicAdd(&g_cnt[g], 1.0f);
}

// ---------------- head: out = (pooled/cnt) @ Wl + bl ----------------
__global__ void k_final(const float* __restrict__ Wl, const float* __restrict__ bl,
                        float* __restrict__ out) {
    int g = blockIdx.x;
    __shared__ float p[32];
    int tid = threadIdx.x;
    if (tid < 32) {
        float c = fmaxf(g_cnt[g], 1.0f);
        p[tid] = g_pooled[g * 32 + tid] / c;
    }
    __syncthreads();
    for (int j = tid; j < 768; j += 256) {
        float acc = bl[j];
        #pragma unroll
        for (int k = 0; k < 32; k++)
            acc = fmaf(p[k], Wl[k * 768 + j], acc);
        out[g * 768 + j] = acc;
    }
}

// ---------------- launch ----------------
extern "C" void kernel_launch(void* const* d_in, const int* in_sizes, int n_in,
                              void* d_out, int out_size) {
    const float* x  = (const float*)d_in[0];
    const float* W1 = (const float*)d_in[1];
    const float* b1 = (const float*)d_in[2];
    const float* W2 = (const float*)d_in[3];
    const float* b2 = (const float*)d_in[4];
    const float* W3 = (const float*)d_in[5];
    const float* b3 = (const float*)d_in[6];
    const float* Wl = (const float*)d_in[7];
    const float* bl = (const float*)d_in[8];
    const int* ei    = (const int*)d_in[9];
    const int* batch = (const int*)d_in[10];
    float* out = (float*)d_out;

    float *p_h1, *p_agg1, *p_h2, *p_agg2, *p_h3, *p_agg3;
    cudaGetSymbolAddress((void**)&p_h1,  g_h1);
    cudaGetSymbolAddress((void**)&p_agg1, g_agg1);
    cudaGetSymbolAddress((void**)&p_h2,  g_h2);
    cudaGetSymbolAddress((void**)&p_agg2, g_agg2);
    cudaGetSymbolAddress((void**)&p_h3,  g_h3);
    cudaGetSymbolAddress((void**)&p_agg3, g_agg3);

    int sm1 = (128 * 128 + 64 * (128 + 4)) * 4;   // ~99 KB
    int sm2 = (128 * 64  + 64 * (128 + 4)) * 4;   // ~66 KB
    int sm3 = (64 * 32   + 64 * (64 + 4))  * 4;   // ~25 KB
    cudaFuncSetAttribute(k_gemm<128, 128, false>, cudaFuncAttributeMaxDynamicSharedMemorySize, sm1);
    cudaFuncSetAttribute(k_gemm<128, 64,  true>,  cudaFuncAttributeMaxDynamicSharedMemorySize, sm2);
    cudaFuncSetAttribute(k_gemm<64,  32,  true>,  cudaFuncAttributeMaxDynamicSharedMemorySize, sm3);

    k_zero<<<(N_NODES + 255) / 256, 256>>>();
    k_degree<<<(N_EDGES + 255) / 256, 256>>>(ei);
    k_dis<<<(N_NODES + 255) / 256, 256>>>();

    // layer 1: 128 -> 128
    k_gemm<128, 128, false><<<N_NODES / 64, 256, sm1>>>(x, W1, nullptr, p_h1, p_agg1);
    k_scatter<128><<<N_EDGES / 8, 256>>>(ei, p_h1, p_agg1);

    // layer 2: 128 -> 64 (relu(agg1*dis + b1) fused into GEMM load)
    k_gemm<128, 64, true><<<N_NODES / 64, 256, sm2>>>(p_agg1, W2, b1, p_h2, p_agg2);
    k_scatter<64><<<N_EDGES / 16, 256>>>(ei, p_h2, p_agg2);

    // layer 3: 64 -> 32
    k_gemm<64, 32, true><<<N_NODES / 64, 256, sm3>>>(p_agg2, W3, b2, p_h3, p_agg3);
    k_scatter<32><<<N_EDGES / 32, 256>>>(ei, p_h3, p_agg3);

    // pool + head
    k_pool<<<N_NODES / 32, 256>>>(batch, b3);
    k_final<<<N_GRAPHS, 256>>>(Wl, bl, out);
}

// round 4
// speedup vs baseline: 1.3647x; 1.3647x over previous
#include <cuda_runtime.h>

#define N_NODES  40000
#define N_EDGES  640000
#define N_GRAPHS 256
#define NB 157            // ceil(40000/256) scan blocks

// ---------------- scratch (static __device__, no allocation) ----------------
__device__ __align__(16) int   g_degi[N_NODES];
__device__ __align__(16) int   g_rowstart[N_NODES];
__device__ __align__(16) int   g_cursor[N_NODES];
__device__ __align__(16) int   g_csr[N_EDGES];
__device__ __align__(16) int   g_bsum[NB];
__device__ __align__(16) int   g_btop[NB];
__device__ __align__(16) float g_dis[N_NODES];
__device__ __align__(16) float g_h1[N_NODES * 128];
__device__ __align__(16) float g_x2[N_NODES * 128];
__device__ __align__(16) float g_h2[N_NODES * 64];
__device__ __align__(16) float g_x3[N_NODES * 64];
__device__ __align__(16) float g_h3[N_NODES * 32];
__device__ __align__(16) float g_pooled[N_GRAPHS * 32];
__device__ __align__(16) float g_cnt[N_GRAPHS];

// ---------------- helpers ----------------
__device__ __forceinline__ void red_add_v4(float* addr, float4 v) {
    asm volatile("red.global.add.v4.f32 [%0], {%1, %2, %3, %4};"
                 :: "l"(addr), "f"(v.x), "f"(v.y), "f"(v.z), "f"(v.w)
                 : "memory");
}
__device__ __forceinline__ void fma2(unsigned long long& a,
                                     unsigned long long x, unsigned long long w) {
    asm("fma.rn.f32x2 %0, %1, %2, %0;" : "+l"(a) : "l"(x), "l"(w));
}
__device__ __forceinline__ unsigned long long pack2(float lo, float hi) {
    return (unsigned long long)__float_as_uint(lo) |
           ((unsigned long long)__float_as_uint(hi) << 32);
}
__device__ __forceinline__ float sum2(unsigned long long a) {
    return __uint_as_float((unsigned)a) + __uint_as_float((unsigned)(a >> 32));
}

// ---------------- prep ----------------
__global__ void k_zero() {
    int i = blockIdx.x * blockDim.x + threadIdx.x;
    if (i < N_NODES) g_degi[i] = 0;
    if (i < N_GRAPHS * 32) g_pooled[i] = 0.f;
    if (i < N_GRAPHS) g_cnt[i] = 0.f;
}

__global__ void k_count(const int* __restrict__ ei, const int* __restrict__ batch) {
    int i = blockIdx.x * blockDim.x + threadIdx.x;
    if (i < N_EDGES) atomicAdd(&g_degi[ei[N_EDGES + i]], 1);
    if (i < N_NODES) atomicAdd(&g_cnt[batch[i]], 1.0f);
}

__global__ void k_scan1() {
    int t = threadIdx.x, i = blockIdx.x * 256 + t;
    int v = (i < N_NODES) ? g_degi[i] : 0;
    for (int off = 16; off; off >>= 1) v += __shfl_down_sync(0xffffffffu, v, off);
    __shared__ int s[8];
    if ((t & 31) == 0) s[t >> 5] = v;
    __syncthreads();
    if (t == 0) {
        int sum = 0;
        #pragma unroll
        for (int j = 0; j < 8; j++) sum += s[j];
        g_bsum[blockIdx.x] = sum;
    }
}

__global__ void k_scan2() {          // 1 block, 256 threads
    __shared__ int s[256];
    int t = threadIdx.x;
    int v = (t < NB) ? g_bsum[t] : 0;
    s[t] = v; __syncthreads();
    for (int off = 1; off < 256; off <<= 1) {
        int a = (t >= off) ? s[t - off] : 0;
        __syncthreads();
        s[t] += a; __syncthreads();
    }
    if (t < NB) g_btop[t] = s[t] - v;  // exclusive
}

__global__ void k_scan3() {
    int t = threadIdx.x, i = blockIdx.x * 256 + t;
    int v = (i < N_NODES) ? g_degi[i] : 0;
    __shared__ int s[256];
    s[t] = v; __syncthreads();
    for (int off = 1; off < 256; off <<= 1) {
        int a = (t >= off) ? s[t - off] : 0;
        __syncthreads();
        s[t] += a; __syncthreads();
    }
    if (i < N_NODES) {
        int ex = s[t] - v + g_btop[blockIdx.x];
        g_rowstart[i] = ex;
        g_cursor[i]   = ex;
        g_dis[i]      = rsqrtf((float)v + 1.0f);
    }
}

__global__ void k_fill(const int* __restrict__ ei) {
    int e = blockIdx.x * blockDim.x + threadIdx.x;
    if (e < N_EDGES) {
        int s = ei[e], d = ei[N_EDGES + e];
        int pos = atomicAdd(&g_cursor[d], 1);
        g_csr[pos] = s;
    }
}

// ---------------- node GEMM: out = (in @ W) * dis[row]  (FFMA2 k-paired) ----------------
template<int K, int N>
__global__ void __launch_bounds__(256, 2)
k_gemm(const float* __restrict__ in, const float* __restrict__ W,
       float* __restrict__ out) {
    constexpr int MT  = 64;
    constexpr int CT  = N / 4;            // col-thread count (4 cols each)
    constexpr int RT  = 256 / CT;
    constexpr int RM  = MT / RT;
    constexpr int P   = K / 2;            // k-pairs
    constexpr int KP4 = K / 4 + 1;        // float4 row stride for Xs

    extern __shared__ char smem[];
    ulonglong2* WsA = (ulonglong2*)smem;            // cols 4ct, 4ct+1 per pair
    ulonglong2* WsB = WsA + P * CT;                 // cols 4ct+2, 4ct+3 per pair
    float4*     Xs4 = (float4*)(WsB + P * CT);

    int tid  = threadIdx.x;
    int row0 = blockIdx.x * MT;

    // W -> smem, k-pair interleaved 64-bit words
    for (int idx = tid; idx < P * CT; idx += 256) {
        int p = idx / CT, c = idx % CT;
        float4 wa = ((const float4*)W)[(2 * p)     * CT + c];
        float4 wb = ((const float4*)W)[(2 * p + 1) * CT + c];
        WsA[idx] = make_ulonglong2(pack2(wa.x, wb.x), pack2(wa.y, wb.y));
        WsB[idx] = make_ulonglong2(pack2(wa.z, wb.z), pack2(wa.w, wb.w));
    }
    // X tile -> smem (padded float4 rows)
    for (int i = tid; i < MT * (K / 4); i += 256) {
        int r = i / (K / 4), q = i % (K / 4);
        Xs4[r * KP4 + q] = ((const float4*)in)[(size_t)row0 * (K / 4) + i];
    }
    __syncthreads();

    int ct = tid % CT;
    int rt = tid / CT;

    unsigned long long acc[RM][4];
    #pragma unroll
    for (int r = 0; r < RM; r++)
        acc[r][0] = acc[r][1] = acc[r][2] = acc[r][3] = 0ull;

    #pragma unroll 4
    for (int q = 0; q < K / 4; q++) {          // 4 k (=2 pairs) per iter
        ulonglong2 wA0 = WsA[(2 * q)     * CT + ct];
        ulonglong2 wB0 = WsB[(2 * q)     * CT + ct];
        ulonglong2 wA1 = WsA[(2 * q + 1) * CT + ct];
        ulonglong2 wB1 = WsB[(2 * q + 1) * CT + ct];
        #pragma unroll
        for (int r = 0; r < RM; r++) {
            ulonglong2 x = *(const ulonglong2*)&Xs4[(rt + r * RT) * KP4 + q];
            fma2(acc[r][0], x.x, wA0.x);
            fma2(acc[r][1], x.x, wA0.y);
            fma2(acc[r][2], x.x, wB0.x);
            fma2(acc[r][3], x.x, wB0.y);
            fma2(acc[r][0], x.y, wA1.x);
            fma2(acc[r][1], x.y, wA1.y);
            fma2(acc[r][2], x.y, wB1.x);
            fma2(acc[r][3], x.y, wB1.y);
        }
    }

    #pragma unroll
    for (int r = 0; r < RM; r++) {
        int row = row0 + rt + r * RT;
        float dr = g_dis[row];
        float4 o = make_float4(sum2(acc[r][0]) * dr, sum2(acc[r][1]) * dr,
                               sum2(acc[r][2]) * dr, sum2(acc[r][3]) * dr);
        ((float4*)out)[(size_t)row * CT + ct] = o;
    }
}

// ---------------- CSR aggregation: out = relu((h[n] + sum_nbr h[s]) * dis + b) ----------------
template<int F, bool POOL>
__global__ void k_agg(const float* __restrict__ h, const float* __restrict__ bias,
                      const int* __restrict__ batch, float* __restrict__ out) {
    constexpr int LPE = F / 4;        // lanes per node
    constexpr int NPW = 32 / LPE;
    int gw   = (blockIdx.x * 256 + threadIdx.x) >> 5;
    int lane = threadIdx.x & 31;
    int sub  = lane / LPE;
    int l    = lane % LPE;
    int node = gw * NPW + sub;
    if (node >= N_NODES) return;

    float4 acc = ((const float4*)h)[(size_t)node * LPE + l];   // self-loop
    int rs = g_rowstart[node];
    int re = rs + g_degi[node];

    int j = rs;
    for (; j + 4 <= re; j += 4) {
        int s0 = g_csr[j], s1 = g_csr[j + 1], s2 = g_csr[j + 2], s3 = g_csr[j + 3];
        float4 a = ((const float4*)h)[(size_t)s0 * LPE + l];
        float4 b = ((const float4*)h)[(size_t)s1 * LPE + l];
        float4 c = ((const float4*)h)[(size_t)s2 * LPE + l];
        float4 d = ((const float4*)h)[(size_t)s3 * LPE + l];
        acc.x += a.x + b.x + c.x + d.x;
        acc.y += a.y + b.y + c.y + d.y;
        acc.z += a.z + b.z + c.z + d.z;
        acc.w += a.w + b.w + c.w + d.w;
    }
    for (; j < re; j++) {
        int s = g_csr[j];
        float4 a = ((const float4*)h)[(size_t)s * LPE + l];
        acc.x += a.x; acc.y += a.y; acc.z += a.z; acc.w += a.w;
    }

    float dr = g_dis[node];
    float4 bv = ((const float4*)bias)[l];
    float4 v = make_float4(fmaxf(fmaf(acc.x, dr, bv.x), 0.f),
                           fmaxf(fmaf(acc.y, dr, bv.y), 0.f),
                           fmaxf(fmaf(acc.z, dr, bv.z), 0.f),
                           fmaxf(fmaf(acc.w, dr, bv.w), 0.f));
    if (POOL) {
        int g = batch[node];
        red_add_v4(g_pooled + g * 32 + l * 4, v);
    } else {
        ((float4*)out)[(size_t)node * LPE + l] = v;
    }
}

// ---------------- head: out = (pooled/cnt) @ Wl + bl ----------------
__global__ void k_final(const float* __restrict__ Wl, const float* __restrict__ bl,
                        float* __restrict__ out) {
    int g = blockIdx.x;
    __shared__ float p[32];
    int tid = threadIdx.x;
    if (tid < 32) {
        float c = fmaxf(g_cnt[g], 1.0f);
        p[tid] = g_pooled[g * 32 + tid] / c;
    }
    __syncthreads();
    for (int j = tid; j < 768; j += 256) {
        float acc = bl[j];
        #pragma unroll
        for (int k = 0; k < 32; k++)
            acc = fmaf(p[k], Wl[k * 768 + j], acc);
        out[g * 768 + j] = acc;
    }
}

// ---------------- launch ----------------
extern "C" void kernel_launch(void* const* d_in, const int* in_sizes, int n_in,
                              void* d_out, int out_size) {
    const float* x  = (const float*)d_in[0];
    const float* W1 = (const float*)d_in[1];
    const float* b1 = (const float*)d_in[2];
    const float* W2 = (const float*)d_in[3];
    const float* b2 = (const float*)d_in[4];
    const float* W3 = (const float*)d_in[5];
    const float* b3 = (const float*)d_in[6];
    const float* Wl = (const float*)d_in[7];
    const float* bl = (const float*)d_in[8];
    const int* ei    = (const int*)d_in[9];
    const int* batch = (const int*)d_in[10];
    float* out = (float*)d_out;

    float *p_h1, *p_x2, *p_h2, *p_x3, *p_h3;
    cudaGetSymbolAddress((void**)&p_h1, g_h1);
    cudaGetSymbolAddress((void**)&p_x2, g_x2);
    cudaGetSymbolAddress((void**)&p_h2, g_h2);
    cudaGetSymbolAddress((void**)&p_x3, g_x3);
    cudaGetSymbolAddress((void**)&p_h3, g_h3);

    // smem bytes: 2 * (K/2)*(N/4)*16  +  64*(K/4+1)*16
    int sm1 = 2 * 64 * 32 * 16 + 64 * 33 * 16;   // 99328
    int sm2 = 2 * 64 * 16 * 16 + 64 * 33 * 16;   // 66560
    int sm3 = 2 * 32 *  8 * 16 + 64 * 17 * 16;   // 25600
    cudaFuncSetAttribute(k_gemm<128, 128>, cudaFuncAttributeMaxDynamicSharedMemorySize, sm1);
    cudaFuncSetAttribute(k_gemm<128, 64>,  cudaFuncAttributeMaxDynamicSharedMemorySize, sm2);
    cudaFuncSetAttribute(k_gemm<64, 32>,   cudaFuncAttributeMaxDynamicSharedMemorySize, sm3);

    // ---- CSR build ----
    k_zero <<<(N_NODES + 255) / 256, 256>>>();
    k_count<<<(N_EDGES + 255) / 256, 256>>>(ei, batch);
    k_scan1<<<NB, 256>>>();
    k_scan2<<<1, 256>>>();
    k_scan3<<<NB, 256>>>();
    k_fill <<<(N_EDGES + 255) / 256, 256>>>(ei);

    // ---- layer 1: 128 -> 128 ----
    k_gemm<128, 128><<<N_NODES / 64, 256, sm1>>>(x, W1, p_h1);
    k_agg<128, false><<<5000, 256>>>(p_h1, b1, batch, p_x2);

    // ---- layer 2: 128 -> 64 ----
    k_gemm<128, 64><<<N_NODES / 64, 256, sm2>>>(p_x2, W2, p_h2);
    k_agg<64, false><<<2500, 256>>>(p_h2, b2, batch, p_x3);

    // ---- layer 3: 64 -> 32 (pool fused) ----
    k_gemm<64, 32><<<N_NODES / 64, 256, sm3>>>(p_x3, W3, p_h3);
    k_agg<32, true><<<1250, 256>>>(p_h3, b3, batch, nullptr);

    // ---- head ----
    k_final<<<N_GRAPHS, 256>>>(Wl, bl, out);
}

// round 7
// speedup vs baseline: 1.4713x; 1.0780x over previous
#include <cuda_runtime.h>
#include <cuda_fp16.h>

#define N_NODES  40000
#define N_EDGES  640000
#define N_GRAPHS 256
#define NB 157            // ceil(40000/256) scan blocks

// ---------------- scratch (static __device__, no allocation) ----------------
__device__ __align__(16) int    g_degi[N_NODES];
__device__ __align__(16) int    g_rowstart[N_NODES];
__device__ __align__(16) int    g_cursor[N_NODES];
__device__ __align__(16) int    g_csr[N_EDGES];
__device__ int    g_base;
__device__ __align__(16) float  g_dis[N_NODES];
__device__ __align__(16) __half g_h1[N_NODES * 128];
__device__ __align__(16) float  g_x2[N_NODES * 128];
__device__ __align__(16) __half g_h2[N_NODES * 64];
__device__ __align__(16) float  g_x3[N_NODES * 64];
__device__ __align__(16) __half g_h3[N_NODES * 32];
__device__ __align__(16) float  g_pooled[N_GRAPHS * 32];
__device__ __align__(16) float  g_cnt[N_GRAPHS];

// ---------------- helpers ----------------
__device__ __forceinline__ void red_add_v4(float* addr, float4 v) {
    asm volatile("red.global.add.v4.f32 [%0], {%1, %2, %3, %4};"
                 :: "l"(addr), "f"(v.x), "f"(v.y), "f"(v.z), "f"(v.w)
                 : "memory");
}
__device__ __forceinline__ void fma2(unsigned long long& a,
                                     unsigned long long x, unsigned long long w) {
    asm("fma.rn.f32x2 %0, %1, %2, %0;" : "+l"(a) : "l"(x), "l"(w));
}
__device__ __forceinline__ unsigned long long pack2(float lo, float hi) {
    return (unsigned long long)__float_as_uint(lo) |
           ((unsigned long long)__float_as_uint(hi) << 32);
}
__device__ __forceinline__ float sum2(unsigned long long a) {
    return __uint_as_float((unsigned)a) + __uint_as_float((unsigned)(a >> 32));
}
__device__ __forceinline__ unsigned h2_bits(__half2 h) {
    unsigned u;
    *(__half2*)&u = h;
    return u;
}
__device__ __forceinline__ void acc_add(float2 acc[4], uint4 v) {
    __half2* p = (__half2*)&v;
    #pragma unroll
    for (int k = 0; k < 4; k++) {
        float2 f = __half22float2(p[k]);
        acc[k].x += f.x; acc[k].y += f.y;
    }
}

// ---------------- prep ----------------
__global__ void k_zero() {
    int i = blockIdx.x * blockDim.x + threadIdx.x;
    if (i < N_NODES) g_degi[i] = 0;
    if (i < N_GRAPHS * 32) g_pooled[i] = 0.f;
    if (i < N_GRAPHS) g_cnt[i] = 0.f;
    if (i == 0) g_base = 0;
}

__global__ void k_count(const int* __restrict__ ei, const int* __restrict__ batch) {
    int i = blockIdx.x * blockDim.x + threadIdx.x;
    if (i < N_EDGES) atomicAdd(&g_degi[ei[N_EDGES + i]], 1);
    if (i < N_NODES) atomicAdd(&g_cnt[batch[i]], 1.0f);
}

// single-kernel scan: block-local inclusive scan + atomic block base.
// cross-block segment placement arbitrary (CSR segments only need per-node
// contiguity); per-node values deterministic.
__global__ void k_scan() {
    int t = threadIdx.x, i = blockIdx.x * 256 + t;
    int lane = t & 31, w = t >> 5;
    int v = (i < N_NODES) ? g_degi[i] : 0;

    int sv = v;
    #pragma unroll
    for (int off = 1; off < 32; off <<= 1) {
        int n = __shfl_up_sync(0xffffffffu, sv, off);
        if (lane >= off) sv += n;
    }
    __shared__ int ws[8];
    if (lane == 31) ws[w] = sv;
    __syncthreads();
    if (w == 0 && lane < 8) {
        int x = ws[lane];
        #pragma unroll
        for (int off = 1; off < 8; off <<= 1) {
            int n = __shfl_up_sync(0xffu, x, off);
            if (lane >= off) x += n;
        }
        ws[lane] = x;
    }
    __syncthreads();
    int incl = sv + (w ? ws[w - 1] : 0);

    __shared__ int base;
    if (t == 255) base = atomicAdd(&g_base, incl);   // incl@255 == block total
    __syncthreads();

    if (i < N_NODES) {
        int ex = base + incl - v;
        g_rowstart[i] = ex;
        g_cursor[i]   = ex;
        g_dis[i]      = rsqrtf((float)v + 1.0f);
    }
}

__global__ void k_fill(const int* __restrict__ ei) {
    int e = blockIdx.x * blockDim.x + threadIdx.x;
    if (e < N_EDGES) {
        int s = ei[e], d = ei[N_EDGES + e];
        int pos = atomicAdd(&g_cursor[d], 1);
        g_csr[pos] = s;
    }
}

// ---------------- node GEMM: out = fp16((in @ W) * dis[row])  (FFMA2 k-paired) ----------------
template<int K, int N>
__global__ void __launch_bounds__(256, 2)
k_gemm(const float* __restrict__ in, const float* __restrict__ W,
       __half* __restrict__ out) {
    constexpr int MT  = 64;
    constexpr int CT  = N / 4;            // col-thread count (4 cols each)
    constexpr int RT  = 256 / CT;
    constexpr int RM  = MT / RT;
    constexpr int P   = K / 2;            // k-pairs
    constexpr int KP4 = K / 4 + 1;        // float4 row stride for Xs

    extern __shared__ char smem[];
    ulonglong2* WsA = (ulonglong2*)smem;            // cols 4ct, 4ct+1 per pair
    ulonglong2* WsB = WsA + P * CT;                 // cols 4ct+2, 4ct+3 per pair
    float4*     Xs4 = (float4*)(WsB + P * CT);

    int tid  = threadIdx.x;
    int row0 = blockIdx.x * MT;

    // W -> smem, k-pair interleaved 64-bit words
    for (int idx = tid; idx < P * CT; idx += 256) {
        int p = idx / CT, c = idx % CT;
        float4 wa = ((const float4*)W)[(2 * p)     * CT + c];
        float4 wb = ((const float4*)W)[(2 * p + 1) * CT + c];
        WsA[idx] = make_ulonglong2(pack2(wa.x, wb.x), pack2(wa.y, wb.y));
        WsB[idx] = make_ulonglong2(pack2(wa.z, wb.z), pack2(wa.w, wb.w));
    }
    // X tile -> smem (padded float4 rows)
    for (int i = tid; i < MT * (K / 4); i += 256) {
        int r = i / (K / 4), q = i % (K / 4);
        Xs4[r * KP4 + q] = ((const float4*)in)[(size_t)row0 * (K / 4) + i];
    }
    __syncthreads();

    int ct = tid % CT;
    int rt = tid / CT;

    unsigned long long acc[RM][4];
    #pragma unroll
    for (int r = 0; r < RM; r++)
        acc[r][0] = acc[r][1] = acc[r][2] = acc[r][3] = 0ull;

    #pragma unroll 4
    for (int q = 0; q < K / 4; q++) {          // 4 k (=2 pairs) per iter
        ulonglong2 wA0 = WsA[(2 * q)     * CT + ct];
        ulonglong2 wB0 = WsB[(2 * q)     * CT + ct];
        ulonglong2 wA1 = WsA[(2 * q + 1) * CT + ct];
        ulonglong2 wB1 = WsB[(2 * q + 1) * CT + ct];
        #pragma unroll
        for (int r = 0; r < RM; r++) {
            ulonglong2 x = *(const ulonglong2*)&Xs4[(rt + r * RT) * KP4 + q];
            fma2(acc[r][0], x.x, wA0.x);
            fma2(acc[r][1], x.x, wA0.y);
            fma2(acc[r][2], x.x, wB0.x);
            fma2(acc[r][3], x.x, wB0.y);
            fma2(acc[r][0], x.y, wA1.x);
            fma2(acc[r][1], x.y, wA1.y);
            fma2(acc[r][2], x.y, wB1.x);
            fma2(acc[r][3], x.y, wB1.y);
        }
    }

    #pragma unroll
    for (int r = 0; r < RM; r++) {
        int row = row0 + rt + r * RT;
        float dr = g_dis[row];
        __half2 lo = __floats2half2_rn(sum2(acc[r][0]) * dr, sum2(acc[r][1]) * dr);
        __half2 hi = __floats2half2_rn(sum2(acc[r][2]) * dr, sum2(acc[r][3]) * dr);
        uint2 o;
        o.x = h2_bits(lo);
        o.y = h2_bits(hi);
        ((uint2*)out)[(size_t)row * CT + ct] = o;
    }
}

// ---------------- CSR aggregation: out = relu((h[n] + sum_nbr h[s]) * dis + b) ----------------
// h is fp16 (8 halves per lane), accumulation fp32, output fp32.
template<int F, bool POOL>
__global__ void k_agg(const __half* __restrict__ h, const float* __restrict__ bias,
                      const int* __restrict__ batch, float* __restrict__ out) {
    constexpr int LPE = F / 8;        // lanes per node (8 features each)
    constexpr int NPW = 32 / LPE;
    int gw   = (blockIdx.x * 256 + threadIdx.x) >> 5;
    int lane = threadIdx.x & 31;
    int sub  = lane / LPE;
    int l    = lane % LPE;
    int node = gw * NPW + sub;
    if (node >= N_NODES) return;

    const uint4* hv = (const uint4*)h;           // row stride = F/8 uint4

    float2 acc[4];
    {
        uint4 sv = hv[(size_t)node * LPE + l];   // self-loop
        __half2* p = (__half2*)&sv;
        #pragma unroll
        for (int k = 0; k < 4; k++) acc[k] = __half22float2(p[k]);
    }

    int rs = g_rowstart[node];
    int re = rs + g_degi[node];

    int j = rs;
    for (; j + 4 <= re; j += 4) {
        int s0 = g_csr[j], s1 = g_csr[j + 1], s2 = g_csr[j + 2], s3 = g_csr[j + 3];
        uint4 a = hv[(size_t)s0 * LPE + l];
        uint4 b = hv[(size_t)s1 * LPE + l];
        uint4 c = hv[(size_t)s2 * LPE + l];
        uint4 d = hv[(size_t)s3 * LPE + l];
        acc_add(acc, a); acc_add(acc, b); acc_add(acc, c); acc_add(acc, d);
    }
    for (; j < re; j++) {
        uint4 a = hv[(size_t)g_csr[j] * LPE + l];
        acc_add(acc, a);
    }

    float dr = g_dis[node];
    float4 b0 = ((const float4*)bias)[l * 2];
    float4 b1 = ((const float4*)bias)[l * 2 + 1];
    float4 v0 = make_float4(fmaxf(fmaf(acc[0].x, dr, b0.x), 0.f),
                            fmaxf(fmaf(acc[0].y, dr, b0.y), 0.f),
                            fmaxf(fmaf(acc[1].x, dr, b0.z), 0.f),
                            fmaxf(fmaf(acc[1].y, dr, b0.w), 0.f));
    float4 v1 = make_float4(fmaxf(fmaf(acc[2].x, dr, b1.x), 0.f),
                            fmaxf(fmaf(acc[2].y, dr, b1.y), 0.f),
                            fmaxf(fmaf(acc[3].x, dr, b1.z), 0.f),
                            fmaxf(fmaf(acc[3].y, dr, b1.w), 0.f));
    if (POOL) {
        int g = batch[node];
        red_add_v4(g_pooled + g * 32 + l * 8, v0);
        red_add_v4(g_pooled + g * 32 + l * 8 + 4, v1);
    } else {
        ((float4*)out)[(size_t)node * (F / 4) + l * 2]     = v0;
        ((float4*)out)[(size_t)node * (F / 4) + l * 2 + 1] = v1;
    }
}

// ---------------- head: out = (pooled/cnt) @ Wl + bl ----------------
__global__ void k_final(const float* __restrict__ Wl, const float* __restrict__ bl,
                        float* __restrict__ out) {
    int g = blockIdx.x;
    __shared__ float p[32];
    int tid = threadIdx.x;
    if (tid < 32) {
        float c = fmaxf(g_cnt[g], 1.0f);
        p[tid] = g_pooled[g * 32 + tid] / c;
    }
    __syncthreads();
    for (int j = tid; j < 768; j += 256) {
        float acc = bl[j];
        #pragma unroll
        for (int k = 0; k < 32; k++)
            acc = fmaf(p[k], Wl[k * 768 + j], acc);
        out[g * 768 + j] = acc;
    }
}

// ---------------- launch ----------------
extern "C" void kernel_launch(void* const* d_in, const int* in_sizes, int n_in,
                              void* d_out, int out_size) {
    const float* x  = (const float*)d_in[0];
    const float* W1 = (const float*)d_in[1];
    const float* b1 = (const float*)d_in[2];
    const float* W2 = (const float*)d_in[3];
    const float* b2 = (const float*)d_in[4];
    const float* W3 = (const float*)d_in[5];
    const float* b3 = (const float*)d_in[6];
    const float* Wl = (const float*)d_in[7];
    const float* bl = (const float*)d_in[8];
    const int* ei    = (const int*)d_in[9];
    const int* batch = (const int*)d_in[10];
    float* out = (float*)d_out;

    __half *p_h1, *p_h2, *p_h3;
    float *p_x2, *p_x3;
    cudaGetSymbolAddress((void**)&p_h1, g_h1);
    cudaGetSymbolAddress((void**)&p_x2, g_x2);
    cudaGetSymbolAddress((void**)&p_h2, g_h2);
    cudaGetSymbolAddress((void**)&p_x3, g_x3);
    cudaGetSymbolAddress((void**)&p_h3, g_h3);

    // smem bytes: 2 * (K/2)*(N/4)*16  +  64*(K/4+1)*16
    int sm1 = 2 * 64 * 32 * 16 + 64 * 33 * 16;   // 99328
    int sm2 = 2 * 64 * 16 * 16 + 64 * 33 * 16;   // 66560
    int sm3 = 2 * 32 *  8 * 16 + 64 * 17 * 16;   // 25600
    cudaFuncSetAttribute(k_gemm<128, 128>, cudaFuncAttributeMaxDynamicSharedMemorySize, sm1);
    cudaFuncSetAttribute(k_gemm<128, 64>,  cudaFuncAttributeMaxDynamicSharedMemorySize, sm2);
    cudaFuncSetAttribute(k_gemm<64, 32>,   cudaFuncAttributeMaxDynamicSharedMemorySize, sm3);

    // ---- CSR build ----
    k_zero <<<(N_NODES + 255) / 256, 256>>>();
    k_count<<<(N_EDGES + 255) / 256, 256>>>(ei, batch);
    k_scan <<<NB, 256>>>();
    k_fill <<<(N_EDGES + 255) / 256, 256>>>(ei);

    // ---- layer 1: 128 -> 128 ----
    k_gemm<128, 128><<<N_NODES / 64, 256, sm1>>>(x, W1, p_h1);
    k_agg<128, false><<<2500, 256>>>(p_h1, b1, batch, p_x2);

    // ---- layer 2: 128 -> 64 ----
    k_gemm<128, 64><<<N_NODES / 64, 256, sm2>>>(p_x2, W2, p_h2);
    k_agg<64, false><<<1250, 256>>>(p_h2, b2, batch, p_x3);

    // ---- layer 3: 64 -> 32 (pool fused) ----
    k_gemm<64, 32><<<N_NODES / 64, 256, sm3>>>(p_x3, W3, p_h3);
    k_agg<32, true><<<625, 256>>>(p_h3, b3, batch, nullptr);

    // ---- head ----
    k_final<<<N_GRAPHS, 256>>>(Wl, bl, out);
}

// round 8
// speedup vs baseline: 1.4721x; 1.0006x over previous
#include <cuda_runtime.h>
#include <cuda_fp16.h>

#define N_NODES  40000
#define N_EDGES  640000
#define N_GRAPHS 256
#define NB 157            // ceil(40000/256) scan blocks
#define CSR_CAP 760000    // N_EDGES + N_NODES*3 worst-case pad-to-4

// ---------------- scratch (static __device__, no allocation) ----------------
__device__ __align__(16) int    g_degi[N_NODES];
__device__ __align__(16) int    g_rowstart[N_NODES];
__device__ __align__(16) int    g_cursor[N_NODES];
__device__ __align__(16) int    g_csr[CSR_CAP];
__device__ int    g_base;
__device__ __align__(16) float  g_dis[N_NODES];
__device__ __align__(16) __half g_h1[N_NODES * 128];
__device__ __align__(16) float  g_x2[N_NODES * 128];
__device__ __align__(16) __half g_h2[N_NODES * 64];
__device__ __align__(16) float  g_x3[N_NODES * 64];
__device__ __align__(16) __half g_h3[N_NODES * 32];
__device__ __align__(16) float  g_pooled[N_GRAPHS * 32];
__device__ __align__(16) float  g_cnt[N_GRAPHS];

// ---------------- helpers ----------------
__device__ __forceinline__ void red_add_v4(float* addr, float4 v) {
    asm volatile("red.global.add.v4.f32 [%0], {%1, %2, %3, %4};"
                 :: "l"(addr), "f"(v.x), "f"(v.y), "f"(v.z), "f"(v.w)
                 : "memory");
}
__device__ __forceinline__ void fma2(unsigned long long& a,
                                     unsigned long long x, unsigned long long w) {
    asm("fma.rn.f32x2 %0, %1, %2, %0;" : "+l"(a) : "l"(x), "l"(w));
}
__device__ __forceinline__ unsigned long long pack2(float lo, float hi) {
    return (unsigned long long)__float_as_uint(lo) |
           ((unsigned long long)__float_as_uint(hi) << 32);
}
__device__ __forceinline__ float sum2(unsigned long long a) {
    return __uint_as_float((unsigned)a) + __uint_as_float((unsigned)(a >> 32));
}
__device__ __forceinline__ unsigned h2_bits(__half2 h) {
    unsigned u;
    *(__half2*)&u = h;
    return u;
}
__device__ __forceinline__ void acc_add(float2 acc[4], uint4 v) {
    __half2* p = (__half2*)&v;
    #pragma unroll
    for (int k = 0; k < 4; k++) {
        float2 f = __half22float2(p[k]);
        acc[k].x += f.x; acc[k].y += f.y;
    }
}

// ---------------- prep ----------------
__global__ void k_zero() {
    int i = blockIdx.x * blockDim.x + threadIdx.x;
    if (i < N_NODES) g_degi[i] = 0;
    if (i < N_GRAPHS * 32) g_pooled[i] = 0.f;
    if (i < N_GRAPHS) g_cnt[i] = 0.f;
    if (i == 0) g_base = 0;
}

__global__ void k_count(const int* __restrict__ ei, const int* __restrict__ batch) {
    int i = blockIdx.x * blockDim.x + threadIdx.x;
    if (i < N_EDGES) atomicAdd(&g_degi[ei[N_EDGES + i]], 1);
    if (i < N_NODES) atomicAdd(&g_cnt[batch[i]], 1.0f);
}

// single-kernel scan over PADDED degrees (each segment rounded up to 4 ints so
// int4 index loads are aligned). cross-block placement arbitrary; per-node
// contiguity is all CSR needs.
__global__ void k_scan() {
    int t = threadIdx.x, i = blockIdx.x * 256 + t;
    int lane = t & 31, w = t >> 5;
    int v  = (i < N_NODES) ? g_degi[i] : 0;
    int pv = (v + 3) & ~3;               // padded degree

    int sv = pv;
    #pragma unroll
    for (int off = 1; off < 32; off <<= 1) {
        int n = __shfl_up_sync(0xffffffffu, sv, off);
        if (lane >= off) sv += n;
    }
    __shared__ int ws[8];
    if (lane == 31) ws[w] = sv;
    __syncthreads();
    if (w == 0 && lane < 8) {
        int x = ws[lane];
        #pragma unroll
        for (int off = 1; off < 8; off <<= 1) {
            int n = __shfl_up_sync(0xffu, x, off);
            if (lane >= off) x += n;
        }
        ws[lane] = x;
    }
    __syncthreads();
    int incl = sv + (w ? ws[w - 1] : 0);

    __shared__ int base;
    if (t == 255) base = atomicAdd(&g_base, incl);   // incl@255 == block total
    __syncthreads();

    if (i < N_NODES) {
        int ex = base + incl - pv;
        g_rowstart[i] = ex;
        g_cursor[i]   = ex;
        g_dis[i]      = rsqrtf((float)v + 1.0f);
    }
}

__global__ void k_fill(const int* __restrict__ ei) {
    int e = blockIdx.x * blockDim.x + threadIdx.x;
    if (e < N_EDGES) {
        int s = ei[e], d = ei[N_EDGES + e];
        int pos = atomicAdd(&g_cursor[d], 1);
        g_csr[pos] = s;
    }
}

// ---------------- node GEMM: out = fp16((in @ W) * dis[row])  (FFMA2 k-paired) ----------------
template<int K, int N>
__global__ void __launch_bounds__(256, 2)
k_gemm(const float* __restrict__ in, const float* __restrict__ W,
       __half* __restrict__ out) {
    constexpr int MT  = 64;
    constexpr int CT  = N / 4;            // col-thread count (4 cols each)
    constexpr int RT  = 256 / CT;
    constexpr int RM  = MT / RT;
    constexpr int P   = K / 2;            // k-pairs
    constexpr int KP4 = K / 4 + 1;        // float4 row stride for Xs

    extern __shared__ char smem[];
    ulonglong2* WsA = (ulonglong2*)smem;            // cols 4ct, 4ct+1 per pair
    ulonglong2* WsB = WsA + P * CT;                 // cols 4ct+2, 4ct+3 per pair
    float4*     Xs4 = (float4*)(WsB + P * CT);

    int tid  = threadIdx.x;
    int row0 = blockIdx.x * MT;

    // W -> smem, k-pair interleaved 64-bit words
    for (int idx = tid; idx < P * CT; idx += 256) {
        int p = idx / CT, c = idx % CT;
        float4 wa = ((const float4*)W)[(2 * p)     * CT + c];
        float4 wb = ((const float4*)W)[(2 * p + 1) * CT + c];
        WsA[idx] = make_ulonglong2(pack2(wa.x, wb.x), pack2(wa.y, wb.y));
        WsB[idx] = make_ulonglong2(pack2(wa.z, wb.z), pack2(wa.w, wb.w));
    }
    // X tile -> smem (padded float4 rows)
    for (int i = tid; i < MT * (K / 4); i += 256) {
        int r = i / (K / 4), q = i % (K / 4);
        Xs4[r * KP4 + q] = ((const float4*)in)[(size_t)row0 * (K / 4) + i];
    }
    __syncthreads();

    int ct = tid % CT;
    int rt = tid / CT;

    unsigned long long acc[RM][4];
    #pragma unroll
    for (int r = 0; r < RM; r++)
        acc[r][0] = acc[r][1] = acc[r][2] = acc[r][3] = 0ull;

    #pragma unroll 4
    for (int q = 0; q < K / 4; q++) {          // 4 k (=2 pairs) per iter
        ulonglong2 wA0 = WsA[(2 * q)     * CT + ct];
        ulonglong2 wB0 = WsB[(2 * q)     * CT + ct];
        ulonglong2 wA1 = WsA[(2 * q + 1) * CT + ct];
        ulonglong2 wB1 = WsB[(2 * q + 1) * CT + ct];
        #pragma unroll
        for (int r = 0; r < RM; r++) {
            ulonglong2 x = *(const ulonglong2*)&Xs4[(rt + r * RT) * KP4 + q];
            fma2(acc[r][0], x.x, wA0.x);
            fma2(acc[r][1], x.x, wA0.y);
            fma2(acc[r][2], x.x, wB0.x);
            fma2(acc[r][3], x.x, wB0.y);
            fma2(acc[r][0], x.y, wA1.x);
            fma2(acc[r][1], x.y, wA1.y);
            fma2(acc[r][2], x.y, wB1.x);
            fma2(acc[r][3], x.y, wB1.y);
        }
    }

    #pragma unroll
    for (int r = 0; r < RM; r++) {
        int row = row0 + rt + r * RT;
        float dr = g_dis[row];
        __half2 lo = __floats2half2_rn(sum2(acc[r][0]) * dr, sum2(acc[r][1]) * dr);
        __half2 hi = __floats2half2_rn(sum2(acc[r][2]) * dr, sum2(acc[r][3]) * dr);
        uint2 o;
        o.x = h2_bits(lo);
        o.y = h2_bits(hi);
        ((uint2*)out)[(size_t)row * CT + ct] = o;
    }
}

// ---------------- CSR aggregation: out = relu((h[n] + sum_nbr h[s]) * dis + b) ----------------
// h fp16 (8 halves per lane), fp32 accumulation, MLP-8 gather loop.
template<int F, bool POOL>
__global__ void k_agg(const __half* __restrict__ h, const float* __restrict__ bias,
                      const int* __restrict__ batch, float* __restrict__ out) {
    constexpr int LPE = F / 8;        // lanes per node (8 features each)
    constexpr int NPW = 32 / LPE;
    int gw   = (blockIdx.x * 256 + threadIdx.x) >> 5;
    int lane = threadIdx.x & 31;
    int sub  = lane / LPE;
    int l    = lane % LPE;
    int node = gw * NPW + sub;
    if (node >= N_NODES) return;

    const uint4* hv = (const uint4*)h;           // row stride = F/8 uint4

    float2 acc[4];
    {
        uint4 sv = __ldg(&hv[(size_t)node * LPE + l]);   // self-loop
        __half2* p = (__half2*)&sv;
        #pragma unroll
        for (int k = 0; k < 4; k++) acc[k] = __half22float2(p[k]);
    }

    int rs = g_rowstart[node];          // 16B-aligned (padded scan)
    int re = rs + g_degi[node];

    int j = rs;
    for (; j + 8 <= re; j += 8) {
        int4 ia = *(const int4*)(g_csr + j);
        int4 ib = *(const int4*)(g_csr + j + 4);
        uint4 v0 = __ldg(&hv[(size_t)ia.x * LPE + l]);
        uint4 v1 = __ldg(&hv[(size_t)ia.y * LPE + l]);
        uint4 v2 = __ldg(&hv[(size_t)ia.z * LPE + l]);
        uint4 v3 = __ldg(&hv[(size_t)ia.w * LPE + l]);
        uint4 v4 = __ldg(&hv[(size_t)ib.x * LPE + l]);
        uint4 v5 = __ldg(&hv[(size_t)ib.y * LPE + l]);
        uint4 v6 = __ldg(&hv[(size_t)ib.z * LPE + l]);
        uint4 v7 = __ldg(&hv[(size_t)ib.w * LPE + l]);
        acc_add(acc, v0); acc_add(acc, v1); acc_add(acc, v2); acc_add(acc, v3);
        acc_add(acc, v4); acc_add(acc, v5); acc_add(acc, v6); acc_add(acc, v7);
    }
    if (j + 4 <= re) {
        int4 ia = *(const int4*)(g_csr + j);
        uint4 v0 = __ldg(&hv[(size_t)ia.x * LPE + l]);
        uint4 v1 = __ldg(&hv[(size_t)ia.y * LPE + l]);
        uint4 v2 = __ldg(&hv[(size_t)ia.z * LPE + l]);
        uint4 v3 = __ldg(&hv[(size_t)ia.w * LPE + l]);
        acc_add(acc, v0); acc_add(acc, v1); acc_add(acc, v2); acc_add(acc, v3);
        j += 4;
    }
    for (; j < re; j++) {
        uint4 a = __ldg(&hv[(size_t)g_csr[j] * LPE + l]);
        acc_add(acc, a);
    }

    float dr = g_dis[node];
    float4 b0 = ((const float4*)bias)[l * 2];
    float4 b1 = ((const float4*)bias)[l * 2 + 1];
    float4 v0 = make_float4(fmaxf(fmaf(acc[0].x, dr, b0.x), 0.f),
                            fmaxf(fmaf(acc[0].y, dr, b0.y), 0.f),
                            fmaxf(fmaf(acc[1].x, dr, b0.z), 0.f),
                            fmaxf(fmaf(acc[1].y, dr, b0.w), 0.f));
    float4 v1 = make_float4(fmaxf(fmaf(acc[2].x, dr, b1.x), 0.f),
                            fmaxf(fmaf(acc[2].y, dr, b1.y), 0.f),
                            fmaxf(fmaf(acc[3].x, dr, b1.z), 0.f),
                            fmaxf(fmaf(acc[3].y, dr, b1.w), 0.f));
    if (POOL) {
        int g = batch[node];
        red_add_v4(g_pooled + g * 32 + l * 8, v0);
        red_add_v4(g_pooled + g * 32 + l * 8 + 4, v1);
    } else {
        ((float4*)out)[(size_t)node * (F / 4) + l * 2]     = v0;
        ((float4*)out)[(size_t)node * (F / 4) + l * 2 + 1] = v1;
    }
}

// ---------------- head: out = (pooled/cnt) @ Wl + bl ----------------
__global__ void k_final(const float* __restrict__ Wl, const float* __restrict__ bl,
                        float* __restrict__ out) {
    int g = blockIdx.x;
    __shared__ float p[32];
    int tid = threadIdx.x;
    if (tid < 32) {
        float c = fmaxf(g_cnt[g], 1.0f);
        p[tid] = g_pooled[g * 32 + tid] / c;
    }
    __syncthreads();
    for (int j = tid; j < 768; j += 256) {
        float acc = bl[j];
        #pragma unroll
        for (int k = 0; k < 32; k++)
            acc = fmaf(p[k], Wl[k * 768 + j], acc);
        out[g * 768 + j] = acc;
    }
}

// ---------------- launch ----------------
extern "C" void kernel_launch(void* const* d_in, const int* in_sizes, int n_in,
                              void* d_out, int out_size) {
    const float* x  = (const float*)d_in[0];
    const float* W1 = (const float*)d_in[1];
    const float* b1 = (const float*)d_in[2];
    const float* W2 = (const float*)d_in[3];
    const float* b2 = (const float*)d_in[4];
    const float* W3 = (const float*)d_in[5];
    const float* b3 = (const float*)d_in[6];
    const float* Wl = (const float*)d_in[7];
    const float* bl = (const float*)d_in[8];
    const int* ei    = (const int*)d_in[9];
    const int* batch = (const int*)d_in[10];
    float* out = (float*)d_out;

    __half *p_h1, *p_h2, *p_h3;
    float *p_x2, *p_x3;
    cudaGetSymbolAddress((void**)&p_h1, g_h1);
    cudaGetSymbolAddress((void**)&p_x2, g_x2);
    cudaGetSymbolAddress((void**)&p_h2, g_h2);
    cudaGetSymbolAddress((void**)&p_x3, g_x3);
    cudaGetSymbolAddress((void**)&p_h3, g_h3);

    // smem bytes: 2 * (K/2)*(N/4)*16  +  64*(K/4+1)*16
    int sm1 = 2 * 64 * 32 * 16 + 64 * 33 * 16;   // 99328
    int sm2 = 2 * 64 * 16 * 16 + 64 * 33 * 16;   // 66560
    int sm3 = 2 * 32 *  8 * 16 + 64 * 17 * 16;   // 25600
    cudaFuncSetAttribute(k_gemm<128, 128>, cudaFuncAttributeMaxDynamicSharedMemorySize, sm1);
    cudaFuncSetAttribute(k_gemm<128, 64>,  cudaFuncAttributeMaxDynamicSharedMemorySize, sm2);
    cudaFuncSetAttribute(k_gemm<64, 32>,   cudaFuncAttributeMaxDynamicSharedMemorySize, sm3);

    // ---- prep + layer 1 (gemm1 ordered before fill so profiled launch #4 = gemm1) ----
    k_zero <<<(N_NODES + 255) / 256, 256>>>();
    k_count<<<(N_EDGES + 255) / 256, 256>>>(ei, batch);
    k_scan <<<NB, 256>>>();
    k_gemm<128, 128><<<N_NODES / 64, 256, sm1>>>(x, W1, p_h1);
    k_fill <<<(N_EDGES + 255) / 256, 256>>>(ei);
    k_agg<128, false><<<2500, 256>>>(p_h1, b1, batch, p_x2);

    // ---- layer 2: 128 -> 64 ----
    k_gemm<128, 64><<<N_NODES / 64, 256, sm2>>>(p_x2, W2, p_h2);
    k_agg<64, false><<<1250, 256>>>(p_h2, b2, batch, p_x3);

    // ---- layer 3: 64 -> 32 (pool fused) ----
    k_gemm<64, 32><<<N_NODES / 64, 256, sm3>>>(p_x3, W3, p_h3);
    k_agg<32, true><<<625, 256>>>(p_h3, b3, batch, nullptr);

    // ---- head ----
    k_final<<<N_GRAPHS, 256>>>(Wl, bl, out);
}

// round 10
// speedup vs baseline: 1.9925x; 1.3535x over previous
#include <cuda_runtime.h>
#include <cuda_fp16.h>
#include <cstdint>

#define N_NODES  40000
#define N_EDGES  640000
#define N_GRAPHS 256
#define NB 157            // ceil(40000/256) scan blocks
#define CSR_CAP 760000    // N_EDGES + N_NODES*3 worst-case pad-to-4

// ---------------- scratch (static __device__, no allocation) ----------------
__device__ __align__(16) int    g_degi[N_NODES];
__device__ __align__(16) int    g_rowstart[N_NODES];
__device__ __align__(16) int    g_cursor[N_NODES];
__device__ __align__(16) int    g_csr[CSR_CAP];
__device__ int    g_base;
__device__ __align__(16) float  g_dis[N_NODES];
__device__ __align__(16) __half g_xh[N_NODES * 128];    // fp16 copy of x
__device__ __align__(16) __half g_w1h[128 * 128];
__device__ __align__(16) __half g_w2h[128 * 64];
__device__ __align__(16) __half g_w3h[64 * 32];
__device__ __align__(16) __half g_h1[N_NODES * 128];
__device__ __align__(16) __half g_x2[N_NODES * 128];
__device__ __align__(16) __half g_h2[N_NODES * 64];
__device__ __align__(16) __half g_x3[N_NODES * 64];
__device__ __align__(16) __half g_h3[N_NODES * 32];
__device__ __align__(16) float  g_pooled[N_GRAPHS * 32];
__device__ __align__(16) float  g_cnt[N_GRAPHS];

// ---------------- helpers ----------------
__device__ __forceinline__ void red_add_v4(float* addr, float4 v) {
    asm volatile("red.global.add.v4.f32 [%0], {%1, %2, %3, %4};"
                 :: "l"(addr), "f"(v.x), "f"(v.y), "f"(v.z), "f"(v.w)
                 : "memory");
}
__device__ __forceinline__ unsigned h2_bits(__half2 h) {
    unsigned u;
    *(__half2*)&u = h;
    return u;
}
__device__ __forceinline__ void acc_add(float2 acc[4], uint4 v) {
    __half2* p = (__half2*)&v;
    #pragma unroll
    for (int k = 0; k < 4; k++) {
        float2 f = __half22float2(p[k]);
        acc[k].x += f.x; acc[k].y += f.y;
    }
}
__device__ __forceinline__ void ldsm_x4(unsigned* r, const __half* p) {
    unsigned a = (unsigned)__cvta_generic_to_shared(p);
    asm volatile("ldmatrix.sync.aligned.m8n8.x4.shared.b16 {%0,%1,%2,%3}, [%4];"
                 : "=r"(r[0]), "=r"(r[1]), "=r"(r[2]), "=r"(r[3]) : "r"(a));
}
__device__ __forceinline__ void ldsm_x4_t(unsigned* r, const __half* p) {
    unsigned a = (unsigned)__cvta_generic_to_shared(p);
    asm volatile("ldmatrix.sync.aligned.m8n8.x4.trans.shared.b16 {%0,%1,%2,%3}, [%4];"
                 : "=r"(r[0]), "=r"(r[1]), "=r"(r[2]), "=r"(r[3]) : "r"(a));
}
__device__ __forceinline__ void mma16816(float* d, const unsigned* a, const unsigned* b) {
    asm volatile(
        "mma.sync.aligned.m16n8k16.row.col.f32.f16.f16.f32 "
        "{%0,%1,%2,%3}, {%4,%5,%6,%7}, {%8,%9}, {%0,%1,%2,%3};"
        : "+f"(d[0]), "+f"(d[1]), "+f"(d[2]), "+f"(d[3])
        : "r"(a[0]), "r"(a[1]), "r"(a[2]), "r"(a[3]), "r"(b[0]), "r"(b[1]));
}

// ---------------- prep ----------------
__global__ void k_zero() {
    int i = blockIdx.x * blockDim.x + threadIdx.x;
    if (i < N_NODES) g_degi[i] = 0;
    if (i < N_GRAPHS * 32) g_pooled[i] = 0.f;
    if (i < N_GRAPHS) g_cnt[i] = 0.f;
    if (i == 0) g_base = 0;
}

__global__ void k_count(const int* __restrict__ ei, const int* __restrict__ batch) {
    int i = blockIdx.x * blockDim.x + threadIdx.x;
    if (i < N_EDGES) atomicAdd(&g_degi[ei[N_EDGES + i]], 1);
    if (i < N_NODES) atomicAdd(&g_cnt[batch[i]], 1.0f);
}

// fp32 -> fp16 convert, 8 elems/thread
__global__ void k_cvt(const float* __restrict__ src, __half* __restrict__ dst, int n8) {
    int i = blockIdx.x * 256 + threadIdx.x;
    if (i < n8) {
        float4 a = ((const float4*)src)[i * 2];
        float4 b = ((const float4*)src)[i * 2 + 1];
        uint4 o;
        o.x = h2_bits(__floats2half2_rn(a.x, a.y));
        o.y = h2_bits(__floats2half2_rn(a.z, a.w));
        o.z = h2_bits(__floats2half2_rn(b.x, b.y));
        o.w = h2_bits(__floats2half2_rn(b.z, b.w));
        ((uint4*)dst)[i] = o;
    }
}

// single-kernel scan over PADDED degrees (segments rounded to 4 ints)
__global__ void k_scan() {
    int t = threadIdx.x, i = blockIdx.x * 256 + t;
    int lane = t & 31, w = t >> 5;
    int v  = (i < N_NODES) ? g_degi[i] : 0;
    int pv = (v + 3) & ~3;

    int sv = pv;
    #pragma unroll
    for (int off = 1; off < 32; off <<= 1) {
        int n = __shfl_up_sync(0xffffffffu, sv, off);
        if (lane >= off) sv += n;
    }
    __shared__ int ws[8];
    if (lane == 31) ws[w] = sv;
    __syncthreads();
    if (w == 0 && lane < 8) {
        int x = ws[lane];
        #pragma unroll
        for (int off = 1; off < 8; off <<= 1) {
            int n = __shfl_up_sync(0xffu, x, off);
            if (lane >= off) x += n;
        }
        ws[lane] = x;
    }
    __syncthreads();
    int incl = sv + (w ? ws[w - 1] : 0);

    __shared__ int base;
    if (t == 255) base = atomicAdd(&g_base, incl);
    __syncthreads();

    if (i < N_NODES) {
        int ex = base + incl - pv;
        g_rowstart[i] = ex;
        g_cursor[i]   = ex;
        g_dis[i]      = rsqrtf((float)v + 1.0f);
    }
}

__global__ void k_fill(const int* __restrict__ ei) {
    int e = blockIdx.x * blockDim.x + threadIdx.x;
    if (e < N_EDGES) {
        int s = ei[e], d = ei[N_EDGES + e];
        int pos = atomicAdd(&g_cursor[d], 1);
        g_csr[pos] = s;
    }
}

// ---------------- HMMA GEMM: out = fp16((in @ W) * dis[row]) ----------------
// in: [M,K] fp16 row-major, W: [K,N] fp16 row-major, out: [M,N] fp16
template<int K, int N, int WM, int WN>
__global__ void __launch_bounds__(256, 2)
k_hgemm(const __half* __restrict__ in, const __half* __restrict__ W,
        __half* __restrict__ out) {
    constexpr int MT  = 128;
    constexpr int XS  = K + 8;       // Xs half-stride (conflict-free ldmatrix)
    constexpr int WS  = N + 8;       // Ws half-stride
    constexpr int MW  = MT / WM;     // warp m extent
    constexpr int NW  = N / WN;      // warp n extent (always 32)
    constexpr int MTL = MW / 16;     // m-tiles per warp
    constexpr int NTL = NW / 8;      // n-tiles per warp (always 4)

    extern __shared__ __half sm[];
    __half* Xs = sm;                 // MT x XS
    __half* Ws = sm + MT * XS;       // K x WS

    int tid  = threadIdx.x;
    int row0 = blockIdx.x * MT;
    int rows = N_NODES - row0; if (rows > MT) rows = MT;

    // load W -> smem
    for (int i = tid; i < K * (N / 8); i += 256) {
        int k = i / (N / 8), c = i % (N / 8);
        *(uint4*)(Ws + k * WS + c * 8) = ((const uint4*)W)[i];
    }
    // load X tile -> smem (zero-padded past end)
    for (int i = tid; i < MT * (K / 8); i += 256) {
        int r = i / (K / 8), c = i % (K / 8);
        uint4 v = make_uint4(0, 0, 0, 0);
        if (r < rows) v = ((const uint4*)in)[(size_t)(row0 + r) * (K / 8) + c];
        *(uint4*)(Xs + r * XS + c * 8) = v;
    }
    __syncthreads();

    int wid = tid >> 5, lane = tid & 31;
    int wm = wid % WM, wn = wid / WM;
    int mbase = wm * MW, nbase = wn * NW;

    float acc[MTL][NTL][4];
    #pragma unroll
    for (int mt = 0; mt < MTL; mt++)
        #pragma unroll
        for (int nt = 0; nt < NTL; nt++)
            acc[mt][nt][0] = acc[mt][nt][1] = acc[mt][nt][2] = acc[mt][nt][3] = 0.f;

    #pragma unroll
    for (int k0 = 0; k0 < K; k0 += 16) {
        unsigned af[MTL][4];
        unsigned bf[NTL][2];
        #pragma unroll
        for (int mt = 0; mt < MTL; mt++) {
            const __half* p = Xs + (mbase + mt * 16 + (lane & 15)) * XS
                                 + k0 + ((lane >> 4) << 3);
            ldsm_x4(af[mt], p);
        }
        #pragma unroll
        for (int p2 = 0; p2 < NTL / 2; p2++) {
            const __half* p = Ws + (k0 + (lane & 15)) * WS
                                 + nbase + p2 * 16 + ((lane >> 4) << 3);
            ldsm_x4_t(&bf[p2 * 2][0], p);
        }
        #pragma unroll
        for (int mt = 0; mt < MTL; mt++)
            #pragma unroll
            for (int nt = 0; nt < NTL; nt++)
                mma16816(acc[mt][nt], af[mt], bf[nt]);
    }

    // epilogue: *dis, fp16, store
    int gr = lane >> 2, tc = (lane & 3) << 1;
    #pragma unroll
    for (int mt = 0; mt < MTL; mt++) {
        int rA = mbase + mt * 16 + gr;
        int rB = rA + 8;
        bool okA = rA < rows, okB = rB < rows;
        float dA = okA ? g_dis[row0 + rA] : 0.f;
        float dB = okB ? g_dis[row0 + rB] : 0.f;
        #pragma unroll
        for (int nt = 0; nt < NTL; nt++) {
            int col = nbase + nt * 8 + tc;
            if (okA)
                *(__half2*)(out + (size_t)(row0 + rA) * N + col) =
                    __floats2half2_rn(acc[mt][nt][0] * dA, acc[mt][nt][1] * dA);
            if (okB)
                *(__half2*)(out + (size_t)(row0 + rB) * N + col) =
                    __floats2half2_rn(acc[mt][nt][2] * dB, acc[mt][nt][3] * dB);
        }
    }
}

// ---------------- CSR aggregation: out = fp16(relu((h[n] + sum h[s]) * dis + b)) ----------------
template<int F, bool POOL>
__global__ void k_agg(const __half* __restrict__ h, const float* __restrict__ bias,
                      const int* __restrict__ batch, __half* __restrict__ out) {
    constexpr int LPE = F / 8;        // lanes per node (8 halves each)
    constexpr int NPW = 32 / LPE;
    int gw   = (blockIdx.x * 256 + threadIdx.x) >> 5;
    int lane = threadIdx.x & 31;
    int sub  = lane / LPE;
    int l    = lane % LPE;
    int node = gw * NPW + sub;
    if (node >= N_NODES) return;

    const uint4* hv = (const uint4*)h;

    float2 acc[4];
    {
        uint4 sv = __ldg(&hv[(size_t)node * LPE + l]);
        __half2* p = (__half2*)&sv;
        #pragma unroll
        for (int k = 0; k < 4; k++) acc[k] = __half22float2(p[k]);
    }

    int rs = g_rowstart[node];
    int re = rs + g_degi[node];

    int j = rs;
    for (; j + 8 <= re; j += 8) {
        int4 ia = *(const int4*)(g_csr + j);
        int4 ib = *(const int4*)(g_csr + j + 4);
        uint4 v0 = __ldg(&hv[(size_t)ia.x * LPE + l]);
        uint4 v1 = __ldg(&hv[(size_t)ia.y * LPE + l]);
        uint4 v2 = __ldg(&hv[(size_t)ia.z * LPE + l]);
        uint4 v3 = __ldg(&hv[(size_t)ia.w * LPE + l]);
        uint4 v4 = __ldg(&hv[(size_t)ib.x * LPE + l]);
        uint4 v5 = __ldg(&hv[(size_t)ib.y * LPE + l]);
        uint4 v6 = __ldg(&hv[(size_t)ib.z * LPE + l]);
        uint4 v7 = __ldg(&hv[(size_t)ib.w * LPE + l]);
        acc_add(acc, v0); acc_add(acc, v1); acc_add(acc, v2); acc_add(acc, v3);
        acc_add(acc, v4); acc_add(acc, v5); acc_add(acc, v6); acc_add(acc, v7);
    }
    if (j + 4 <= re) {
        int4 ia = *(const int4*)(g_csr + j);
        uint4 v0 = __ldg(&hv[(size_t)ia.x * LPE + l]);
        uint4 v1 = __ldg(&hv[(size_t)ia.y * LPE + l]);
        uint4 v2 = __ldg(&hv[(size_t)ia.z * LPE + l]);
        uint4 v3 = __ldg(&hv[(size_t)ia.w * LPE + l]);
        acc_add(acc, v0); acc_add(acc, v1); acc_add(acc, v2); acc_add(acc, v3);
        j += 4;
    }
    for (; j < re; j++) {
        uint4 a = __ldg(&hv[(size_t)g_csr[j] * LPE + l]);
        acc_add(acc, a);
    }

    float dr = g_dis[node];
    float4 b0 = ((const float4*)bias)[l * 2];
    float4 b1 = ((const float4*)bias)[l * 2 + 1];
    float4 v0 = make_float4(fmaxf(fmaf(acc[0].x, dr, b0.x), 0.f),
                            fmaxf(fmaf(acc[0].y, dr, b0.y), 0.f),
                            fmaxf(fmaf(acc[1].x, dr, b0.z), 0.f),
                            fmaxf(fmaf(acc[1].y, dr, b0.w), 0.f));
    float4 v1 = make_float4(fmaxf(fmaf(acc[2].x, dr, b1.x), 0.f),
                            fmaxf(fmaf(acc[2].y, dr, b1.y), 0.f),
                            fmaxf(fmaf(acc[3].x, dr, b1.z), 0.f),
                            fmaxf(fmaf(acc[3].y, dr, b1.w), 0.f));
    if (POOL) {
        int g = batch[node];
        red_add_v4(g_pooled + g * 32 + l * 8, v0);
        red_add_v4(g_pooled + g * 32 + l * 8 + 4, v1);
    } else {
        uint4 o;
        o.x = h2_bits(__floats2half2_rn(v0.x, v0.y));
        o.y = h2_bits(__floats2half2_rn(v0.z, v0.w));
        o.z = h2_bits(__floats2half2_rn(v1.x, v1.y));
        o.w = h2_bits(__floats2half2_rn(v1.z, v1.w));
        ((uint4*)out)[(size_t)node * LPE + l] = o;
    }
}

// ---------------- head: out = (pooled/cnt) @ Wl + bl ----------------
__global__ void k_final(const float* __restrict__ Wl, const float* __restrict__ bl,
                        float* __restrict__ out) {
    int g = blockIdx.x;
    __shared__ float p[32];
    int tid = threadIdx.x;
    if (tid < 32) {
        float c = fmaxf(g_cnt[g], 1.0f);
        p[tid] = g_pooled[g * 32 + tid] / c;
    }
    __syncthreads();
    for (int j = tid; j < 768; j += 256) {
        float acc = bl[j];
        #pragma unroll
        for (int k = 0; k < 32; k++)
            acc = fmaf(p[k], Wl[k * 768 + j], acc);
        out[g * 768 + j] = acc;
    }
}

// ---------------- launch ----------------
extern "C" void kernel_launch(void* const* d_in, const int* in_sizes, int n_in,
                              void* d_out, int out_size) {
    const float* x  = (const float*)d_in[0];
    const float* W1 = (const float*)d_in[1];
    const float* b1 = (const float*)d_in[2];
    const float* W2 = (const float*)d_in[3];
    const float* b2 = (const float*)d_in[4];
    const float* W3 = (const float*)d_in[5];
    const float* b3 = (const float*)d_in[6];
    const float* Wl = (const float*)d_in[7];
    const float* bl = (const float*)d_in[8];
    const int* ei    = (const int*)d_in[9];
    const int* batch = (const int*)d_in[10];
    float* out = (float*)d_out;

    __half *p_xh, *p_w1h, *p_w2h, *p_w3h, *p_h1, *p_x2, *p_h2, *p_x3, *p_h3;
    cudaGetSymbolAddress((void**)&p_xh,  g_xh);
    cudaGetSymbolAddress((void**)&p_w1h, g_w1h);
    cudaGetSymbolAddress((void**)&p_w2h, g_w2h);
    cudaGetSymbolAddress((void**)&p_w3h, g_w3h);
    cudaGetSymbolAddress((void**)&p_h1,  g_h1);
    cudaGetSymbolAddress((void**)&p_x2,  g_x2);
    cudaGetSymbolAddress((void**)&p_h2,  g_h2);
    cudaGetSymbolAddress((void**)&p_x3,  g_x3);
    cudaGetSymbolAddress((void**)&p_h3,  g_h3);

    // smem: (MT*(K+8) + K*(N+8)) * 2 bytes
    int s1 = (128 * 136 + 128 * 136) * 2;   // 69632
    int s2 = (128 * 136 + 128 * 72) * 2;    // 53248
    int s3 = (128 * 72 + 64 * 40) * 2;      // 23552
    cudaFuncSetAttribute(k_hgemm<128, 128, 2, 4>,
                         cudaFuncAttributeMaxDynamicSharedMemorySize, s1);
    cudaFuncSetAttribute(k_hgemm<128, 64, 4, 2>,
                         cudaFuncAttributeMaxDynamicSharedMemorySize, s2);
    cudaFuncSetAttribute(k_hgemm<64, 32, 8, 1>,
                         cudaFuncAttributeMaxDynamicSharedMemorySize, s3);

    int mblocks = (N_NODES + 127) / 128;    // 313

    // ---- prep + converts ----
    k_zero <<<(N_NODES + 255) / 256, 256>>>();
    k_count<<<(N_EDGES + 255) / 256, 256>>>(ei, batch);
    k_scan <<<NB, 256>>>();
    k_cvt  <<<2500, 256>>>(x, p_xh, N_NODES * 128 / 8);
    k_cvt  <<<8, 256>>>(W1, p_w1h, 128 * 128 / 8);
    k_cvt  <<<4, 256>>>(W2, p_w2h, 128 * 64 / 8);
    k_cvt  <<<1, 256>>>(W3, p_w3h, 64 * 32 / 8);
    k_fill <<<(N_EDGES + 255) / 256, 256>>>(ei);

    // ---- layer 1: 128 -> 128 ----
    k_hgemm<128, 128, 2, 4><<<mblocks, 256, s1>>>(p_xh, p_w1h, p_h1);
    k_agg<128, false><<<2500, 256>>>(p_h1, b1, batch, p_x2);

    // ---- layer 2: 128 -> 64 ----
    k_hgemm<128, 64, 4, 2><<<mblocks, 256, s2>>>(p_x2, p_w2h, p_h2);
    k_agg<64, false><<<1250, 256>>>(p_h2, b2, batch, p_x3);

    // ---- layer 3: 64 -> 32 (pool fused) ----
    k_hgemm<64, 32, 8, 1><<<mblocks, 256, s3>>>(p_x3, p_w3h, p_h3);
    k_agg<32, true><<<625, 256>>>(p_h3, b3, batch, nullptr);

    // ---- head ----
    k_final<<<N_GRAPHS, 256>>>(Wl, bl, out);
}

// round 11
// speedup vs baseline: 2.1064x; 1.0571x over previous
#include <cuda_runtime.h>
#include <cuda_fp16.h>
#include <cstdint>

#define N_NODES  40000
#define N_EDGES  640000
#define N_GRAPHS 256
#define NB 157            // ceil(40000/256) scan blocks
#define CSR_CAP 760000    // N_EDGES + N_NODES*3 worst-case pad-to-4

// ---------------- scratch (static __device__, no allocation) ----------------
__device__ __align__(16) int    g_degi[N_NODES];
__device__ __align__(16) int    g_rowstart[N_NODES];
__device__ __align__(16) int    g_cursor[N_NODES];
__device__ __align__(16) int    g_csr[CSR_CAP];
__device__ int    g_base;
__device__ __align__(16) float  g_dis[N_NODES];
__device__ __align__(16) __half g_h1[N_NODES * 128];
__device__ __align__(16) __half g_x2[N_NODES * 128];
__device__ __align__(16) __half g_h2[N_NODES * 64];
__device__ __align__(16) __half g_x3[N_NODES * 64];
__device__ __align__(16) __half g_h3[N_NODES * 32];
__device__ __align__(16) float  g_pooled[N_GRAPHS * 32];
__device__ __align__(16) float  g_cnt[N_GRAPHS];

// ---------------- helpers ----------------
__device__ __forceinline__ void red_add_v4(float* addr, float4 v) {
    asm volatile("red.global.add.v4.f32 [%0], {%1, %2, %3, %4};"
                 :: "l"(addr), "f"(v.x), "f"(v.y), "f"(v.z), "f"(v.w)
                 : "memory");
}
__device__ __forceinline__ unsigned h2_bits(__half2 h) {
    unsigned u;
    *(__half2*)&u = h;
    return u;
}
__device__ __forceinline__ uint4 cvt8(float4 a, float4 b) {
    uint4 o;
    o.x = h2_bits(__floats2half2_rn(a.x, a.y));
    o.y = h2_bits(__floats2half2_rn(a.z, a.w));
    o.z = h2_bits(__floats2half2_rn(b.x, b.y));
    o.w = h2_bits(__floats2half2_rn(b.z, b.w));
    return o;
}
__device__ __forceinline__ void acc_add(float2 acc[4], uint4 v) {
    __half2* p = (__half2*)&v;
    #pragma unroll
    for (int k = 0; k < 4; k++) {
        float2 f = __half22float2(p[k]);
        acc[k].x += f.x; acc[k].y += f.y;
    }
}
__device__ __forceinline__ void ldsm_x4(unsigned* r, const __half* p) {
    unsigned a = (unsigned)__cvta_generic_to_shared(p);
    asm volatile("ldmatrix.sync.aligned.m8n8.x4.shared.b16 {%0,%1,%2,%3}, [%4];"
                 : "=r"(r[0]), "=r"(r[1]), "=r"(r[2]), "=r"(r[3]) : "r"(a));
}
__device__ __forceinline__ void ldsm_x4_t(unsigned* r, const __half* p) {
    unsigned a = (unsigned)__cvta_generic_to_shared(p);
    asm volatile("ldmatrix.sync.aligned.m8n8.x4.trans.shared.b16 {%0,%1,%2,%3}, [%4];"
                 : "=r"(r[0]), "=r"(r[1]), "=r"(r[2]), "=r"(r[3]) : "r"(a));
}
__device__ __forceinline__ void mma16816(float* d, const unsigned* a, const unsigned* b) {
    asm volatile(
        "mma.sync.aligned.m16n8k16.row.col.f32.f16.f16.f32 "
        "{%0,%1,%2,%3}, {%4,%5,%6,%7}, {%8,%9}, {%0,%1,%2,%3};"
        : "+f"(d[0]), "+f"(d[1]), "+f"(d[2]), "+f"(d[3])
        : "r"(a[0]), "r"(a[1]), "r"(a[2]), "r"(a[3]), "r"(b[0]), "r"(b[1]));
}

// ---------------- prep ----------------
__global__ void k_zero() {
    int i = blockIdx.x * blockDim.x + threadIdx.x;
    if (i < N_NODES) g_degi[i] = 0;
    if (i < N_GRAPHS * 32) g_pooled[i] = 0.f;
    if (i < N_GRAPHS) g_cnt[i] = 0.f;
    if (i == 0) g_base = 0;
}

__global__ void k_count(const int* __restrict__ ei, const int* __restrict__ batch) {
    int i = blockIdx.x * blockDim.x + threadIdx.x;
    if (i < N_EDGES) atomicAdd(&g_degi[ei[N_EDGES + i]], 1);
    if (i < N_NODES) atomicAdd(&g_cnt[batch[i]], 1.0f);
}

// single-kernel scan over PADDED degrees (segments rounded to 4 ints)
__global__ void k_scan() {
    int t = threadIdx.x, i = blockIdx.x * 256 + t;
    int lane = t & 31, w = t >> 5;
    int v  = (i < N_NODES) ? g_degi[i] : 0;
    int pv = (v + 3) & ~3;

    int sv = pv;
    #pragma unroll
    for (int off = 1; off < 32; off <<= 1) {
        int n = __shfl_up_sync(0xffffffffu, sv, off);
        if (lane >= off) sv += n;
    }
    __shared__ int ws[8];
    if (lane == 31) ws[w] = sv;
    __syncthreads();
    if (w == 0 && lane < 8) {
        int x = ws[lane];
        #pragma unroll
        for (int off = 1; off < 8; off <<= 1) {
            int n = __shfl_up_sync(0xffu, x, off);
            if (lane >= off) x += n;
        }
        ws[lane] = x;
    }
    __syncthreads();
    int incl = sv + (w ? ws[w - 1] : 0);

    __shared__ int base;
    if (t == 255) base = atomicAdd(&g_base, incl);
    __syncthreads();

    if (i < N_NODES) {
        int ex = base + incl - pv;
        g_rowstart[i] = ex;
        g_cursor[i]   = ex;
        g_dis[i]      = rsqrtf((float)v + 1.0f);
    }
}

__global__ void k_fill(const int* __restrict__ ei) {
    int e = blockIdx.x * blockDim.x + threadIdx.x;
    if (e < N_EDGES) {
        int s = ei[e], d = ei[N_EDGES + e];
        int pos = atomicAdd(&g_cursor[d], 1);
        g_csr[pos] = s;
    }
}

// ---------------- HMMA GEMM: out = fp16((in @ W) * dis[row]) ----------------
// in: [M,K] TIN row-major (fp32 or fp16), W: [K,N] fp32 row-major, out: [M,N] fp16
// fp32 inputs are converted to fp16 during the smem staging stores.
template<int K, int N, int WM, int WN, typename TIN>
__global__ void __launch_bounds__(256, 2)
k_hgemm(const TIN* __restrict__ in, const float* __restrict__ W,
        __half* __restrict__ out) {
    constexpr int MT  = 128;
    constexpr int XS  = K + 8;       // Xs half-stride (conflict-free ldmatrix)
    constexpr int WS  = N + 8;       // Ws half-stride
    constexpr int MW  = MT / WM;     // warp m extent
    constexpr int NW  = N / WN;      // warp n extent (always 32)
    constexpr int MTL = MW / 16;     // m-tiles per warp
    constexpr int NTL = NW / 8;      // n-tiles per warp (always 4)

    extern __shared__ __half sm[];
    __half* Xs = sm;                 // MT x XS
    __half* Ws = sm + MT * XS;       // K x WS

    int tid  = threadIdx.x;
    int row0 = blockIdx.x * MT;
    int rows = N_NODES - row0; if (rows > MT) rows = MT;

    // load W (fp32) -> smem fp16
    for (int i = tid; i < K * (N / 8); i += 256) {
        int k = i / (N / 8), c = i % (N / 8);
        float4 a = ((const float4*)W)[i * 2];
        float4 b = ((const float4*)W)[i * 2 + 1];
        *(uint4*)(Ws + k * WS + c * 8) = cvt8(a, b);
    }
    // load X tile -> smem (convert if fp32; zero-pad past end)
    for (int i = tid; i < MT * (K / 8); i += 256) {
        int r = i / (K / 8), c = i % (K / 8);
        uint4 v = make_uint4(0, 0, 0, 0);
        if (r < rows) {
            if (sizeof(TIN) == 4) {
                const float4* src = (const float4*)in;
                float4 a = src[((size_t)(row0 + r) * (K / 8) + c) * 2];
                float4 b = src[((size_t)(row0 + r) * (K / 8) + c) * 2 + 1];
                v = cvt8(a, b);
            } else {
                v = ((const uint4*)in)[(size_t)(row0 + r) * (K / 8) + c];
            }
        }
        *(uint4*)(Xs + r * XS + c * 8) = v;
    }
    __syncthreads();

    int wid = tid >> 5, lane = tid & 31;
    int wm = wid % WM, wn = wid / WM;
    int mbase = wm * MW, nbase = wn * NW;

    float acc[MTL][NTL][4];
    #pragma unroll
    for (int mt = 0; mt < MTL; mt++)
        #pragma unroll
        for (int nt = 0; nt < NTL; nt++)
            acc[mt][nt][0] = acc[mt][nt][1] = acc[mt][nt][2] = acc[mt][nt][3] = 0.f;

    #pragma unroll
    for (int k0 = 0; k0 < K; k0 += 16) {
        unsigned af[MTL][4];
        unsigned bf[NTL][2];
        #pragma unroll
        for (int mt = 0; mt < MTL; mt++) {
            const __half* p = Xs + (mbase + mt * 16 + (lane & 15)) * XS
                                 + k0 + ((lane >> 4) << 3);
            ldsm_x4(af[mt], p);
        }
        #pragma unroll
        for (int p2 = 0; p2 < NTL / 2; p2++) {
            const __half* p = Ws + (k0 + (lane & 15)) * WS
                                 + nbase + p2 * 16 + ((lane >> 4) << 3);
            ldsm_x4_t(&bf[p2 * 2][0], p);
        }
        #pragma unroll
        for (int mt = 0; mt < MTL; mt++)
            #pragma unroll
            for (int nt = 0; nt < NTL; nt++)
                mma16816(acc[mt][nt], af[mt], bf[nt]);
    }

    // epilogue: *dis, fp16, store
    int gr = lane >> 2, tc = (lane & 3) << 1;
    #pragma unroll
    for (int mt = 0; mt < MTL; mt++) {
        int rA = mbase + mt * 16 + gr;
        int rB = rA + 8;
        bool okA = rA < rows, okB = rB < rows;
        float dA = okA ? g_dis[row0 + rA] : 0.f;
        float dB = okB ? g_dis[row0 + rB] : 0.f;
        #pragma unroll
        for (int nt = 0; nt < NTL; nt++) {
            int col = nbase + nt * 8 + tc;
            if (okA)
                *(__half2*)(out + (size_t)(row0 + rA) * N + col) =
                    __floats2half2_rn(acc[mt][nt][0] * dA, acc[mt][nt][1] * dA);
            if (okB)
                *(__half2*)(out + (size_t)(row0 + rB) * N + col) =
                    __floats2half2_rn(acc[mt][nt][2] * dB, acc[mt][nt][3] * dB);
        }
    }
}

// ---------------- CSR aggregation: out = fp16(relu((h[n] + sum h[s]) * dis + b)) ----------------
template<int F, bool POOL>
__global__ void k_agg(const __half* __restrict__ h, const float* __restrict__ bias,
                      const int* __restrict__ batch, __half* __restrict__ out) {
    constexpr int LPE = F / 8;        // lanes per node (8 halves each)
    constexpr int NPW = 32 / LPE;
    int gw   = (blockIdx.x * 256 + threadIdx.x) >> 5;
    int lane = threadIdx.x & 31;
    int sub  = lane / LPE;
    int l    = lane % LPE;
    int node = gw * NPW + sub;
    if (node >= N_NODES) return;

    const uint4* hv = (const uint4*)h;

    float2 acc[4];
    {
        uint4 sv = __ldg(&hv[(size_t)node * LPE + l]);
        __half2* p = (__half2*)&sv;
        #pragma unroll
        for (int k = 0; k < 4; k++) acc[k] = __half22float2(p[k]);
    }

    int rs = g_rowstart[node];
    int re = rs + g_degi[node];

    int j = rs;
    for (; j + 8 <= re; j += 8) {
        int4 ia = *(const int4*)(g_csr + j);
        int4 ib = *(const int4*)(g_csr + j + 4);
        uint4 v0 = __ldg(&hv[(size_t)ia.x * LPE + l]);
        uint4 v1 = __ldg(&hv[(size_t)ia.y * LPE + l]);
        uint4 v2 = __ldg(&hv[(size_t)ia.z * LPE + l]);
        uint4 v3 = __ldg(&hv[(size_t)ia.w * LPE + l]);
        uint4 v4 = __ldg(&hv[(size_t)ib.x * LPE + l]);
        uint4 v5 = __ldg(&hv[(size_t)ib.y * LPE + l]);
        uint4 v6 = __ldg(&hv[(size_t)ib.z * LPE + l]);
        uint4 v7 = __ldg(&hv[(size_t)ib.w * LPE + l]);
        acc_add(acc, v0); acc_add(acc, v1); acc_add(acc, v2); acc_add(acc, v3);
        acc_add(acc, v4); acc_add(acc, v5); acc_add(acc, v6); acc_add(acc, v7);
    }
    if (j + 4 <= re) {
        int4 ia = *(const int4*)(g_csr + j);
        uint4 v0 = __ldg(&hv[(size_t)ia.x * LPE + l]);
        uint4 v1 = __ldg(&hv[(size_t)ia.y * LPE + l]);
        uint4 v2 = __ldg(&hv[(size_t)ia.z * LPE + l]);
        uint4 v3 = __ldg(&hv[(size_t)ia.w * LPE + l]);
        acc_add(acc, v0); acc_add(acc, v1); acc_add(acc, v2); acc_add(acc, v3);
        j += 4;
    }
    for (; j < re; j++) {
        uint4 a = __ldg(&hv[(size_t)g_csr[j] * LPE + l]);
        acc_add(acc, a);
    }

    float dr = g_dis[node];
    float4 b0 = ((const float4*)bias)[l * 2];
    float4 b1 = ((const float4*)bias)[l * 2 + 1];
    float4 v0 = make_float4(fmaxf(fmaf(acc[0].x, dr, b0.x), 0.f),
                            fmaxf(fmaf(acc[0].y, dr, b0.y), 0.f),
                            fmaxf(fmaf(acc[1].x, dr, b0.z), 0.f),
                            fmaxf(fmaf(acc[1].y, dr, b0.w), 0.f));
    float4 v1 = make_float4(fmaxf(fmaf(acc[2].x, dr, b1.x), 0.f),
                            fmaxf(fmaf(acc[2].y, dr, b1.y), 0.f),
                            fmaxf(fmaf(acc[3].x, dr, b1.z), 0.f),
                            fmaxf(fmaf(acc[3].y, dr, b1.w), 0.f));
    if (POOL) {
        int g = batch[node];
        red_add_v4(g_pooled + g * 32 + l * 8, v0);
        red_add_v4(g_pooled + g * 32 + l * 8 + 4, v1);
    } else {
        uint4 o;
        o.x = h2_bits(__floats2half2_rn(v0.x, v0.y));
        o.y = h2_bits(__floats2half2_rn(v0.z, v0.w));
        o.z = h2_bits(__floats2half2_rn(v1.x, v1.y));
        o.w = h2_bits(__floats2half2_rn(v1.z, v1.w));
        ((uint4*)out)[(size_t)node * LPE + l] = o;
    }
}

// ---------------- head: out = (pooled/cnt) @ Wl + bl ----------------
__global__ void k_final(const float* __restrict__ Wl, const float* __restrict__ bl,
                        float* __restrict__ out) {
    int g = blockIdx.x;
    __shared__ float p[32];
    int tid = threadIdx.x;
    if (tid < 32) {
        float c = fmaxf(g_cnt[g], 1.0f);
        p[tid] = g_pooled[g * 32 + tid] / c;
    }
    __syncthreads();
    for (int j = tid; j < 768; j += 256) {
        float acc = bl[j];
        #pragma unroll
        for (int k = 0; k < 32; k++)
            acc = fmaf(p[k], Wl[k * 768 + j], acc);
        out[g * 768 + j] = acc;
    }
}

// ---------------- launch ----------------
extern "C" void kernel_launch(void* const* d_in, const int* in_sizes, int n_in,
                              void* d_out, int out_size) {
    const float* x  = (const float*)d_in[0];
    const float* W1 = (const float*)d_in[1];
    const float* b1 = (const float*)d_in[2];
    const float* W2 = (const float*)d_in[3];
    const float* b2 = (const float*)d_in[4];
    const float* W3 = (const float*)d_in[5];
    const float* b3 = (const float*)d_in[6];
    const float* Wl = (const float*)d_in[7];
    const float* bl = (const float*)d_in[8];
    const int* ei    = (const int*)d_in[9];
    const int* batch = (const int*)d_in[10];
    float* out = (float*)d_out;

    __half *p_h1, *p_x2, *p_h2, *p_x3, *p_h3;
    cudaGetSymbolAddress((void**)&p_h1, g_h1);
    cudaGetSymbolAddress((void**)&p_x2, g_x2);
    cudaGetSymbolAddress((void**)&p_h2, g_h2);
    cudaGetSymbolAddress((void**)&p_x3, g_x3);
    cudaGetSymbolAddress((void**)&p_h3, g_h3);

    // smem: (MT*(K+8) + K*(N+8)) * 2 bytes
    int s1 = (128 * 136 + 128 * 136) * 2;   // 69632
    int s2 = (128 * 136 + 128 * 72) * 2;    // 53248
    int s3 = (128 * 72 + 64 * 40) * 2;      // 23552
    cudaFuncSetAttribute(k_hgemm<128, 128, 2, 4, float>,
                         cudaFuncAttributeMaxDynamicSharedMemorySize, s1);
    cudaFuncSetAttribute(k_hgemm<128, 64, 4, 2, __half>,
                         cudaFuncAttributeMaxDynamicSharedMemorySize, s2);
    cudaFuncSetAttribute(k_hgemm<64, 32, 8, 1, __half>,
                         cudaFuncAttributeMaxDynamicSharedMemorySize, s3);

    int mblocks = (N_NODES + 127) / 128;    // 313

    // ---- prep ----
    k_zero <<<(N_NODES + 255) / 256, 256>>>();
    k_count<<<(N_EDGES + 255) / 256, 256>>>(ei, batch);
    k_scan <<<NB, 256>>>();

    // ---- layer 1: 128 -> 128 (x fp32 converted in-GEMM; launch #4 = gemm1) ----
    k_hgemm<128, 128, 2, 4, float><<<mblocks, 256, s1>>>(x, W1, p_h1);
    k_fill <<<(N_EDGES + 255) / 256, 256>>>(ei);
    k_agg<128, false><<<2500, 256>>>(p_h1, b1, batch, p_x2);

    // ---- layer 2: 128 -> 64 ----
    k_hgemm<128, 64, 4, 2, __half><<<mblocks, 256, s2>>>(p_x2, W2, p_h2);
    k_agg<64, false><<<1250, 256>>>(p_h2, b2, batch, p_x3);

    // ---- layer 3: 64 -> 32 (pool fused) ----
    k_hgemm<64, 32, 8, 1, __half><<<mblocks, 256, s3>>>(p_x3, W3, p_h3);
    k_agg<32, true><<<625, 256>>>(p_h3, b3, batch, nullptr);

    // ---- head ----
    k_final<<<N_GRAPHS, 256>>>(Wl, bl, out);
}

// round 12
// speedup vs baseline: 2.1123x; 1.0028x over previous
#include <cuda_runtime.h>
#include <cuda_fp16.h>
#include <cstdint>

#define N_NODES  40000
#define N_EDGES  640000
#define N_GRAPHS 256
#define NB 157            // ceil(40000/256) scan blocks
#define CSR_CAP 760000    // N_EDGES + N_NODES*3 worst-case pad-to-4

// ---------------- scratch (static __device__, no allocation) ----------------
__device__ __align__(16) int    g_degi[N_NODES];
__device__ __align__(16) int    g_rowstart[N_NODES];
__device__ __align__(16) int    g_cursor[N_NODES];
__device__ __align__(16) int    g_csr[CSR_CAP];
__device__ int    g_base;
__device__ __align__(16) float  g_dis[N_NODES];
__device__ __align__(16) __half g_h1[N_NODES * 128];
__device__ __align__(16) __half g_x2[N_NODES * 128];
__device__ __align__(16) __half g_h2[N_NODES * 64];
__device__ __align__(16) __half g_x3[N_NODES * 64];
__device__ __align__(16) __half g_h3[N_NODES * 32];
__device__ __align__(16) float  g_pooled[N_GRAPHS * 32];
__device__ __align__(16) float  g_cnt[N_GRAPHS];

// ---------------- helpers ----------------
__device__ __forceinline__ void red_add_v4(float* addr, float4 v) {
    asm volatile("red.global.add.v4.f32 [%0], {%1, %2, %3, %4};"
                 :: "l"(addr), "f"(v.x), "f"(v.y), "f"(v.z), "f"(v.w)
                 : "memory");
}
__device__ __forceinline__ unsigned h2_bits(__half2 h) {
    unsigned u;
    *(__half2*)&u = h;
    return u;
}
__device__ __forceinline__ uint4 cvt8(float4 a, float4 b) {
    uint4 o;
    o.x = h2_bits(__floats2half2_rn(a.x, a.y));
    o.y = h2_bits(__floats2half2_rn(a.z, a.w));
    o.z = h2_bits(__floats2half2_rn(b.x, b.y));
    o.w = h2_bits(__floats2half2_rn(b.z, b.w));
    return o;
}
__device__ __forceinline__ void acc_add(float2 acc[4], uint4 v) {
    __half2* p = (__half2*)&v;
    #pragma unroll
    for (int k = 0; k < 4; k++) {
        float2 f = __half22float2(p[k]);
        acc[k].x += f.x; acc[k].y += f.y;
    }
}
__device__ __forceinline__ void ldsm_x4(unsigned* r, const __half* p) {
    unsigned a = (unsigned)__cvta_generic_to_shared(p);
    asm volatile("ldmatrix.sync.aligned.m8n8.x4.shared.b16 {%0,%1,%2,%3}, [%4];"
                 : "=r"(r[0]), "=r"(r[1]), "=r"(r[2]), "=r"(r[3]) : "r"(a));
}
__device__ __forceinline__ void ldsm_x4_t(unsigned* r, const __half* p) {
    unsigned a = (unsigned)__cvta_generic_to_shared(p);
    asm volatile("ldmatrix.sync.aligned.m8n8.x4.trans.shared.b16 {%0,%1,%2,%3}, [%4];"
                 : "=r"(r[0]), "=r"(r[1]), "=r"(r[2]), "=r"(r[3]) : "r"(a));
}
__device__ __forceinline__ void mma16816(float* d, const unsigned* a, const unsigned* b) {
    asm volatile(
        "mma.sync.aligned.m16n8k16.row.col.f32.f16.f16.f32 "
        "{%0,%1,%2,%3}, {%4,%5,%6,%7}, {%8,%9}, {%0,%1,%2,%3};"
        : "+f"(d[0]), "+f"(d[1]), "+f"(d[2]), "+f"(d[3])
        : "r"(a[0]), "r"(a[1]), "r"(a[2]), "r"(a[3]), "r"(b[0]), "r"(b[1]));
}

// ---------------- prep ----------------
__global__ void k_zero() {
    int i = blockIdx.x * blockDim.x + threadIdx.x;
    if (i < N_NODES) g_degi[i] = 0;
    if (i < N_GRAPHS * 32) g_pooled[i] = 0.f;
    if (i < N_GRAPHS) g_cnt[i] = 0.f;
    if (i == 0) g_base = 0;
}

__global__ void k_count(const int* __restrict__ ei, const int* __restrict__ batch) {
    int i = blockIdx.x * blockDim.x + threadIdx.x;
    if (i < N_EDGES) atomicAdd(&g_degi[ei[N_EDGES + i]], 1);
    if (i < N_NODES) atomicAdd(&g_cnt[batch[i]], 1.0f);
}

// single-kernel scan over PADDED degrees (segments rounded to 4 ints)
__global__ void k_scan() {
    int t = threadIdx.x, i = blockIdx.x * 256 + t;
    int lane = t & 31, w = t >> 5;
    int v  = (i < N_NODES) ? g_degi[i] : 0;
    int pv = (v + 3) & ~3;

    int sv = pv;
    #pragma unroll
    for (int off = 1; off < 32; off <<= 1) {
        int n = __shfl_up_sync(0xffffffffu, sv, off);
        if (lane >= off) sv += n;
    }
    __shared__ int ws[8];
    if (lane == 31) ws[w] = sv;
    __syncthreads();
    if (w == 0 && lane < 8) {
        int x = ws[lane];
        #pragma unroll
        for (int off = 1; off < 8; off <<= 1) {
            int n = __shfl_up_sync(0xffu, x, off);
            if (lane >= off) x += n;
        }
        ws[lane] = x;
    }
    __syncthreads();
    int incl = sv + (w ? ws[w - 1] : 0);

    __shared__ int base;
    if (t == 255) base = atomicAdd(&g_base, incl);
    __syncthreads();

    if (i < N_NODES) {
        int ex = base + incl - pv;
        g_rowstart[i] = ex;
        g_cursor[i]   = ex;
        g_dis[i]      = rsqrtf((float)v + 1.0f);
    }
}

__global__ void k_fill(const int* __restrict__ ei) {
    int e = blockIdx.x * blockDim.x + threadIdx.x;
    if (e < N_EDGES) {
        int s = ei[e], d = ei[N_EDGES + e];
        int pos = atomicAdd(&g_cursor[d], 1);
        g_csr[pos] = s;
    }
}

// ---------------- HMMA GEMM: out = fp16((in @ W) * dis[row]) ----------------
// in: [M,K] TIN row-major (fp32 or fp16), W: [K,N] fp32 row-major, out: [M,N] fp16
template<int K, int N, int WM, int WN, int THREADS, typename TIN>
__global__ void __launch_bounds__(THREADS, 2)
k_hgemm(const TIN* __restrict__ in, const float* __restrict__ W,
        __half* __restrict__ out) {
    constexpr int MT  = 128;
    constexpr int XS  = K + 8;       // Xs half-stride (conflict-free ldmatrix)
    constexpr int WS  = N + 8;       // Ws half-stride
    constexpr int MW  = MT / WM;     // warp m extent
    constexpr int NW  = N / WN;      // warp n extent
    constexpr int MTL = MW / 16;     // m-tiles per warp
    constexpr int NTL = NW / 8;      // n-tiles per warp
    static_assert(WM * WN == THREADS / 32, "warp layout");
    static_assert(MTL >= 1 && NTL >= 2 && NTL % 2 == 0, "tile shape");

    extern __shared__ __half sm[];
    __half* Xs = sm;                 // MT x XS
    __half* Ws = sm + MT * XS;       // K x WS

    int tid  = threadIdx.x;
    int row0 = blockIdx.x * MT;
    int rows = N_NODES - row0; if (rows > MT) rows = MT;

    // load W (fp32) -> smem fp16
    for (int i = tid; i < K * (N / 8); i += THREADS) {
        int k = i / (N / 8), c = i % (N / 8);
        float4 a = ((const float4*)W)[i * 2];
        float4 b = ((const float4*)W)[i * 2 + 1];
        *(uint4*)(Ws + k * WS + c * 8) = cvt8(a, b);
    }
    // load X tile -> smem (convert if fp32; zero-pad past end)
    for (int i = tid; i < MT * (K / 8); i += THREADS) {
        int r = i / (K / 8), c = i % (K / 8);
        uint4 v = make_uint4(0, 0, 0, 0);
        if (r < rows) {
            if (sizeof(TIN) == 4) {
                const float4* src = (const float4*)in;
                float4 a = src[((size_t)(row0 + r) * (K / 8) + c) * 2];
                float4 b = src[((size_t)(row0 + r) * (K / 8) + c) * 2 + 1];
                v = cvt8(a, b);
            } else {
                v = ((const uint4*)in)[(size_t)(row0 + r) * (K / 8) + c];
            }
        }
        *(uint4*)(Xs + r * XS + c * 8) = v;
    }
    __syncthreads();

    int wid = tid >> 5, lane = tid & 31;
    int wm = wid % WM, wn = wid / WM;
    int mbase = wm * MW, nbase = wn * NW;

    float acc[MTL][NTL][4];
    #pragma unroll
    for (int mt = 0; mt < MTL; mt++)
        #pragma unroll
        for (int nt = 0; nt < NTL; nt++)
            acc[mt][nt][0] = acc[mt][nt][1] = acc[mt][nt][2] = acc[mt][nt][3] = 0.f;

    #pragma unroll
    for (int k0 = 0; k0 < K; k0 += 16) {
        unsigned af[MTL][4];
        unsigned bf[NTL][2];
        #pragma unroll
        for (int mt = 0; mt < MTL; mt++) {
            const __half* p = Xs + (mbase + mt * 16 + (lane & 15)) * XS
                                 + k0 + ((lane >> 4) << 3);
            ldsm_x4(af[mt], p);
        }
        #pragma unroll
        for (int p2 = 0; p2 < NTL / 2; p2++) {
            const __half* p = Ws + (k0 + (lane & 15)) * WS
                                 + nbase + p2 * 16 + ((lane >> 4) << 3);
            ldsm_x4_t(&bf[p2 * 2][0], p);
        }
        #pragma unroll
        for (int mt = 0; mt < MTL; mt++)
            #pragma unroll
            for (int nt = 0; nt < NTL; nt++)
                mma16816(acc[mt][nt], af[mt], bf[nt]);
    }

    // epilogue: *dis, fp16, store
    int gr = lane >> 2, tc = (lane & 3) << 1;
    #pragma unroll
    for (int mt = 0; mt < MTL; mt++) {
        int rA = mbase + mt * 16 + gr;
        int rB = rA + 8;
        bool okA = rA < rows, okB = rB < rows;
        float dA = okA ? g_dis[row0 + rA] : 0.f;
        float dB = okB ? g_dis[row0 + rB] : 0.f;
        #pragma unroll
        for (int nt = 0; nt < NTL; nt++) {
            int col = nbase + nt * 8 + tc;
            if (okA)
                *(__half2*)(out + (size_t)(row0 + rA) * N + col) =
                    __floats2half2_rn(acc[mt][nt][0] * dA, acc[mt][nt][1] * dA);
            if (okB)
                *(__half2*)(out + (size_t)(row0 + rB) * N + col) =
                    __floats2half2_rn(acc[mt][nt][2] * dB, acc[mt][nt][3] * dB);
        }
    }
}

// ---------------- CSR aggregation: out = fp16(relu((h[n] + sum h[s]) * dis + b)) ----------------
template<int F, bool POOL>
__global__ void k_agg(const __half* __restrict__ h, const float* __restrict__ bias,
                      const int* __restrict__ batch, __half* __restrict__ out) {
    constexpr int LPE = F / 8;        // lanes per node (8 halves each)
    constexpr int NPW = 32 / LPE;
    int gw   = (blockIdx.x * 256 + threadIdx.x) >> 5;
    int lane = threadIdx.x & 31;
    int sub  = lane / LPE;
    int l    = lane % LPE;
    int node = gw * NPW + sub;
    if (node >= N_NODES) return;

    const uint4* hv = (const uint4*)h;

    float2 acc[4];
    {
        uint4 sv = __ldg(&hv[(size_t)node * LPE + l]);
        __half2* p = (__half2*)&sv;
        #pragma unroll
        for (int k = 0; k < 4; k++) acc[k] = __half22float2(p[k]);
    }

    int rs = g_rowstart[node];
    int re = rs + g_degi[node];

    int j = rs;
    for (; j + 8 <= re; j += 8) {
        int4 ia = *(const int4*)(g_csr + j);
        int4 ib = *(const int4*)(g_csr + j + 4);
        uint4 v0 = __ldg(&hv[(size_t)ia.x * LPE + l]);
        uint4 v1 = __ldg(&hv[(size_t)ia.y * LPE + l]);
        uint4 v2 = __ldg(&hv[(size_t)ia.z * LPE + l]);
        uint4 v3 = __ldg(&hv[(size_t)ia.w * LPE + l]);
        uint4 v4 = __ldg(&hv[(size_t)ib.x * LPE + l]);
        uint4 v5 = __ldg(&hv[(size_t)ib.y * LPE + l]);
        uint4 v6 = __ldg(&hv[(size_t)ib.z * LPE + l]);
        uint4 v7 = __ldg(&hv[(size_t)ib.w * LPE + l]);
        acc_add(acc, v0); acc_add(acc, v1); acc_add(acc, v2); acc_add(acc, v3);
        acc_add(acc, v4); acc_add(acc, v5); acc_add(acc, v6); acc_add(acc, v7);
    }
    if (j + 4 <= re) {
        int4 ia = *(const int4*)(g_csr + j);
        uint4 v0 = __ldg(&hv[(size_t)ia.x * LPE + l]);
        uint4 v1 = __ldg(&hv[(size_t)ia.y * LPE + l]);
        uint4 v2 = __ldg(&hv[(size_t)ia.z * LPE + l]);
        uint4 v3 = __ldg(&hv[(size_t)ia.w * LPE + l]);
        acc_add(acc, v0); acc_add(acc, v1); acc_add(acc, v2); acc_add(acc, v3);
        j += 4;
    }
    for (; j < re; j++) {
        uint4 a = __ldg(&hv[(size_t)g_csr[j] * LPE + l]);
        acc_add(acc, a);
    }

    float dr = g_dis[node];
    float4 b0 = ((const float4*)bias)[l * 2];
    float4 b1 = ((const float4*)bias)[l * 2 + 1];
    float4 v0 = make_float4(fmaxf(fmaf(acc[0].x, dr, b0.x), 0.f),
                            fmaxf(fmaf(acc[0].y, dr, b0.y), 0.f),
                            fmaxf(fmaf(acc[1].x, dr, b0.z), 0.f),
                            fmaxf(fmaf(acc[1].y, dr, b0.w), 0.f));
    float4 v1 = make_float4(fmaxf(fmaf(acc[2].x, dr, b1.x), 0.f),
                            fmaxf(fmaf(acc[2].y, dr, b1.y), 0.f),
                            fmaxf(fmaf(acc[3].x, dr, b1.z), 0.f),
                            fmaxf(fmaf(acc[3].y, dr, b1.w), 0.f));
    if (POOL) {
        int g = batch[node];
        red_add_v4(g_pooled + g * 32 + l * 8, v0);
        red_add_v4(g_pooled + g * 32 + l * 8 + 4, v1);
    } else {
        uint4 o;
        o.x = h2_bits(__floats2half2_rn(v0.x, v0.y));
        o.y = h2_bits(__floats2half2_rn(v0.z, v0.w));
        o.z = h2_bits(__floats2half2_rn(v1.x, v1.y));
        o.w = h2_bits(__floats2half2_rn(v1.z, v1.w));
        ((uint4*)out)[(size_t)node * LPE + l] = o;
    }
}

// ---------------- head: out = (pooled/cnt) @ Wl + bl ----------------
__global__ void k_final(const float* __restrict__ Wl, const float* __restrict__ bl,
                        float* __restrict__ out) {
    int g = blockIdx.x;
    __shared__ float p[32];
    int tid = threadIdx.x;
    if (tid < 32) {
        float c = fmaxf(g_cnt[g], 1.0f);
        p[tid] = g_pooled[g * 32 + tid] / c;
    }
    __syncthreads();
    for (int j = tid; j < 768; j += 256) {
        float acc = bl[j];
        #pragma unroll
        for (int k = 0; k < 32; k++)
            acc = fmaf(p[k], Wl[k * 768 + j], acc);
        out[g * 768 + j] = acc;
    }
}

// ---------------- launch ----------------
extern "C" void kernel_launch(void* const* d_in, const int* in_sizes, int n_in,
                              void* d_out, int out_size) {
    const float* x  = (const float*)d_in[0];
    const float* W1 = (const float*)d_in[1];
    const float* b1 = (const float*)d_in[2];
    const float* W2 = (const float*)d_in[3];
    const float* b2 = (const float*)d_in[4];
    const float* W3 = (const float*)d_in[5];
    const float* b3 = (const float*)d_in[6];
    const float* Wl = (const float*)d_in[7];
    const float* bl = (const float*)d_in[8];
    const int* ei    = (const int*)d_in[9];
    const int* batch = (const int*)d_in[10];
    float* out = (float*)d_out;

    __half *p_h1, *p_x2, *p_h2, *p_x3, *p_h3;
    cudaGetSymbolAddress((void**)&p_h1, g_h1);
    cudaGetSymbolAddress((void**)&p_x2, g_x2);
    cudaGetSymbolAddress((void**)&p_h2, g_h2);
    cudaGetSymbolAddress((void**)&p_x3, g_x3);
    cudaGetSymbolAddress((void**)&p_h3, g_h3);

    // smem: (MT*(K+8) + K*(N+8)) * 2 bytes
    int s1 = (128 * 136 + 128 * 136) * 2;   // 69632
    int s2 = (128 * 136 + 128 * 72) * 2;    // 53248
    int s3 = (128 * 72 + 64 * 40) * 2;      // 23552
    cudaFuncSetAttribute(k_hgemm<128, 128, 8, 2, 512, float>,
                         cudaFuncAttributeMaxDynamicSharedMemorySize, s1);
    cudaFuncSetAttribute(k_hgemm<128, 64, 8, 2, 512, __half>,
                         cudaFuncAttributeMaxDynamicSharedMemorySize, s2);
    cudaFuncSetAttribute(k_hgemm<64, 32, 8, 1, 256, __half>,
                         cudaFuncAttributeMaxDynamicSharedMemorySize, s3);

    int mblocks = (N_NODES + 127) / 128;    // 313

    // ---- prep ----
    k_zero <<<(N_NODES + 255) / 256, 256>>>();
    k_count<<<(N_EDGES + 255) / 256, 256>>>(ei, batch);
    k_scan <<<NB, 256>>>();

    // ---- layer 1: 128 -> 128 (x fp32 converted in-GEMM; launch #4 = gemm1) ----
    k_hgemm<128, 128, 8, 2, 512, float><<<mblocks, 512, s1>>>(x, W1, p_h1);
    k_fill <<<(N_EDGES + 255) / 256, 256>>>(ei);
    k_agg<128, false><<<2500, 256>>>(p_h1, b1, batch, p_x2);

    // ---- layer 2: 128 -> 64 ----
    k_hgemm<128, 64, 8, 2, 512, __half><<<mblocks, 512, s2>>>(p_x2, W2, p_h2);
    k_agg<64, false><<<1250, 256>>>(p_h2, b2, batch, p_x3);

    // ---- layer 3: 64 -> 32 (pool fused) ----
    k_hgemm<64, 32, 8, 1, 256, __half><<<mblocks, 256, s3>>>(p_x3, W3, p_h3);
    k_agg<32, true><<<625, 256>>>(p_h3, b3, batch, nullptr);

    // ---- head ----
    k_final<<<N_GRAPHS, 256>>>(Wl, bl, out);
}

// round 13
// speedup vs baseline: 2.1849x; 1.0343x over previous
#include <cuda_runtime.h>
#include <cuda_fp16.h>
#include <cstdint>

#define N_NODES  40000
#define N_EDGES  640000
#define N_GRAPHS 256
#define NB 157            // ceil(40000/256) scan blocks
#define CSR_CAP 760000    // N_EDGES + N_NODES*3 worst-case pad-to-4

// ---------------- scratch (static __device__, no allocation) ----------------
__device__ __align__(16) int    g_degi[N_NODES];
__device__ __align__(16) int    g_rowstart[N_NODES];
__device__ __align__(16) int    g_cursor[N_NODES];
__device__ __align__(16) int    g_csr[CSR_CAP];
__device__ int    g_base;
__device__ __align__(16) float  g_dis[N_NODES];
__device__ __align__(16) __half g_w1h[128 * 128];
__device__ __align__(16) __half g_w2h[128 * 64];
__device__ __align__(16) __half g_w3h[64 * 32];
__device__ __align__(16) __half g_h1[N_NODES * 128];
__device__ __align__(16) __half g_x2[N_NODES * 128];
__device__ __align__(16) __half g_h2[N_NODES * 64];
__device__ __align__(16) __half g_x3[N_NODES * 64];
__device__ __align__(16) __half g_h3[N_NODES * 32];
__device__ __align__(16) float  g_pooled[N_GRAPHS * 32];
__device__ __align__(16) float  g_cnt[N_GRAPHS];

// ---------------- helpers ----------------
__device__ __forceinline__ void red_add_v4(float* addr, float4 v) {
    asm volatile("red.global.add.v4.f32 [%0], {%1, %2, %3, %4};"
                 :: "l"(addr), "f"(v.x), "f"(v.y), "f"(v.z), "f"(v.w)
                 : "memory");
}
__device__ __forceinline__ unsigned h2_bits(__half2 h) {
    unsigned u;
    *(__half2*)&u = h;
    return u;
}
__device__ __forceinline__ uint4 cvt8(float4 a, float4 b) {
    uint4 o;
    o.x = h2_bits(__floats2half2_rn(a.x, a.y));
    o.y = h2_bits(__floats2half2_rn(a.z, a.w));
    o.z = h2_bits(__floats2half2_rn(b.x, b.y));
    o.w = h2_bits(__floats2half2_rn(b.z, b.w));
    return o;
}
__device__ __forceinline__ void acc_add(float2 acc[4], uint4 v) {
    __half2* p = (__half2*)&v;
    #pragma unroll
    for (int k = 0; k < 4; k++) {
        float2 f = __half22float2(p[k]);
        acc[k].x += f.x; acc[k].y += f.y;
    }
}
__device__ __forceinline__ void ldsm_x4(unsigned* r, const __half* p) {
    unsigned a = (unsigned)__cvta_generic_to_shared(p);
    asm volatile("ldmatrix.sync.aligned.m8n8.x4.shared.b16 {%0,%1,%2,%3}, [%4];"
                 : "=r"(r[0]), "=r"(r[1]), "=r"(r[2]), "=r"(r[3]) : "r"(a));
}
__device__ __forceinline__ void ldsm_x4_t(unsigned* r, const __half* p) {
    unsigned a = (unsigned)__cvta_generic_to_shared(p);
    asm volatile("ldmatrix.sync.aligned.m8n8.x4.trans.shared.b16 {%0,%1,%2,%3}, [%4];"
                 : "=r"(r[0]), "=r"(r[1]), "=r"(r[2]), "=r"(r[3]) : "r"(a));
}
__device__ __forceinline__ void mma16816(float* d, const unsigned* a, const unsigned* b) {
    asm volatile(
        "mma.sync.aligned.m16n8k16.row.col.f32.f16.f16.f32 "
        "{%0,%1,%2,%3}, {%4,%5,%6,%7}, {%8,%9}, {%0,%1,%2,%3};"
        : "+f"(d[0]), "+f"(d[1]), "+f"(d[2]), "+f"(d[3])
        : "r"(a[0]), "r"(a[1]), "r"(a[2]), "r"(a[3]), "r"(b[0]), "r"(b[1]));
}

// ---------------- prep ----------------
// zero scratch + convert all three W matrices to fp16 (no extra launch)
__global__ void k_zero(const float* __restrict__ W1, const float* __restrict__ W2,
                       const float* __restrict__ W3) {
    int i = blockIdx.x * blockDim.x + threadIdx.x;
    if (i < N_NODES) g_degi[i] = 0;
    if (i < N_GRAPHS * 32) g_pooled[i] = 0.f;
    if (i < N_GRAPHS) g_cnt[i] = 0.f;
    if (i == 0) g_base = 0;
    if (i < 8192)
        ((__half2*)g_w1h)[i] = __float22half2_rn(((const float2*)W1)[i]);
    else if (i < 12288)
        ((__half2*)g_w2h)[i - 8192] = __float22half2_rn(((const float2*)W2)[i - 8192]);
    else if (i < 13312)
        ((__half2*)g_w3h)[i - 12288] = __float22half2_rn(((const float2*)W3)[i - 12288]);
}

// 4 edges per thread (int4 index loads); grid 625*256 = 160000 = N_EDGES/4
__global__ void k_count(const int* __restrict__ ei, const int* __restrict__ batch) {
    int i = blockIdx.x * blockDim.x + threadIdx.x;
    int4 d4 = ((const int4*)(ei + N_EDGES))[i];
    atomicAdd(&g_degi[d4.x], 1);
    atomicAdd(&g_degi[d4.y], 1);
    atomicAdd(&g_degi[d4.z], 1);
    atomicAdd(&g_degi[d4.w], 1);
    if (i < N_NODES) atomicAdd(&g_cnt[batch[i]], 1.0f);
}

// single-kernel scan over PADDED degrees (segments rounded to 4 ints)
__global__ void k_scan() {
    int t = threadIdx.x, i = blockIdx.x * 256 + t;
    int lane = t & 31, w = t >> 5;
    int v  = (i < N_NODES) ? g_degi[i] : 0;
    int pv = (v + 3) & ~3;

    int sv = pv;
    #pragma unroll
    for (int off = 1; off < 32; off <<= 1) {
        int n = __shfl_up_sync(0xffffffffu, sv, off);
        if (lane >= off) sv += n;
    }
    __shared__ int ws[8];
    if (lane == 31) ws[w] = sv;
    __syncthreads();
    if (w == 0 && lane < 8) {
        int x = ws[lane];
        #pragma unroll
        for (int off = 1; off < 8; off <<= 1) {
            int n = __shfl_up_sync(0xffu, x, off);
            if (lane >= off) x += n;
        }
        ws[lane] = x;
    }
    __syncthreads();
    int incl = sv + (w ? ws[w - 1] : 0);

    __shared__ int base;
    if (t == 255) base = atomicAdd(&g_base, incl);
    __syncthreads();

    if (i < N_NODES) {
        int ex = base + incl - pv;
        g_rowstart[i] = ex;
        g_cursor[i]   = ex;
        g_dis[i]      = rsqrtf((float)v + 1.0f);
    }
}

// 4 edges per thread; grid 625*256 = 160000
__global__ void k_fill(const int* __restrict__ ei) {
    int i = blockIdx.x * blockDim.x + threadIdx.x;
    int4 s4 = ((const int4*)ei)[i];
    int4 d4 = ((const int4*)(ei + N_EDGES))[i];
    g_csr[atomicAdd(&g_cursor[d4.x], 1)] = s4.x;
    g_csr[atomicAdd(&g_cursor[d4.y], 1)] = s4.y;
    g_csr[atomicAdd(&g_cursor[d4.z], 1)] = s4.z;
    g_csr[atomicAdd(&g_cursor[d4.w], 1)] = s4.w;
}

// ---------------- HMMA GEMM: out = fp16((in @ W) * dis[row]) ----------------
// in: [M,K] TIN row-major (fp32 or fp16), W: [K,N] TW row-major, out: [M,N] fp16
template<int K, int N, int WM, int WN, int THREADS, typename TIN, typename TW>
__global__ void __launch_bounds__(THREADS, 2)
k_hgemm(const TIN* __restrict__ in, const TW* __restrict__ W,
        __half* __restrict__ out) {
    constexpr int MT  = 128;
    constexpr int XS  = K + 8;       // Xs half-stride (conflict-free ldmatrix)
    constexpr int WS  = N + 8;       // Ws half-stride
    constexpr int MW  = MT / WM;     // warp m extent
    constexpr int NW  = N / WN;      // warp n extent
    constexpr int MTL = MW / 16;     // m-tiles per warp
    constexpr int NTL = NW / 8;      // n-tiles per warp
    static_assert(WM * WN == THREADS / 32, "warp layout");
    static_assert(MTL >= 1 && NTL >= 2 && NTL % 2 == 0, "tile shape");

    extern __shared__ __half sm[];
    __half* Xs = sm;                 // MT x XS
    __half* Ws = sm + MT * XS;       // K x WS

    int tid  = threadIdx.x;
    int row0 = blockIdx.x * MT;
    int rows = N_NODES - row0; if (rows > MT) rows = MT;

    // X tile first (DRAM long pole), then W (L2-resident)
    for (int i = tid; i < MT * (K / 8); i += THREADS) {
        int r = i / (K / 8), c = i % (K / 8);
        uint4 v = make_uint4(0, 0, 0, 0);
        if (r < rows) {
            if (sizeof(TIN) == 4) {
                const float4* src = (const float4*)in;
                float4 a = src[((size_t)(row0 + r) * (K / 8) + c) * 2];
                float4 b = src[((size_t)(row0 + r) * (K / 8) + c) * 2 + 1];
                v = cvt8(a, b);
            } else {
                v = ((const uint4*)in)[(size_t)(row0 + r) * (K / 8) + c];
            }
        }
        *(uint4*)(Xs + r * XS + c * 8) = v;
    }
    for (int i = tid; i < K * (N / 8); i += THREADS) {
        int k = i / (N / 8), c = i % (N / 8);
        uint4 wv;
        if (sizeof(TW) == 4) {
            float4 a = ((const float4*)W)[i * 2];
            float4 b = ((const float4*)W)[i * 2 + 1];
            wv = cvt8(a, b);
        } else {
            wv = ((const uint4*)W)[i];
        }
        *(uint4*)(Ws + k * WS + c * 8) = wv;
    }
    __syncthreads();

    int wid = tid >> 5, lane = tid & 31;
    int wm = wid % WM, wn = wid / WM;
    int mbase = wm * MW, nbase = wn * NW;

    float acc[MTL][NTL][4];
    #pragma unroll
    for (int mt = 0; mt < MTL; mt++)
        #pragma unroll
        for (int nt = 0; nt < NTL; nt++)
            acc[mt][nt][0] = acc[mt][nt][1] = acc[mt][nt][2] = acc[mt][nt][3] = 0.f;

    #pragma unroll
    for (int k0 = 0; k0 < K; k0 += 16) {
        unsigned af[MTL][4];
        unsigned bf[NTL][2];
        #pragma unroll
        for (int mt = 0; mt < MTL; mt++) {
            const __half* p = Xs + (mbase + mt * 16 + (lane & 15)) * XS
                                 + k0 + ((lane >> 4) << 3);
            ldsm_x4(af[mt], p);
        }
        #pragma unroll
        for (int p2 = 0; p2 < NTL / 2; p2++) {
            const __half* p = Ws + (k0 + (lane & 15)) * WS
                                 + nbase + p2 * 16 + ((lane >> 4) << 3);
            ldsm_x4_t(&bf[p2 * 2][0], p);
        }
        #pragma unroll
        for (int mt = 0; mt < MTL; mt++)
            #pragma unroll
            for (int nt = 0; nt < NTL; nt++)
                mma16816(acc[mt][nt], af[mt], bf[nt]);
    }

    // epilogue: *dis, fp16, store
    int gr = lane >> 2, tc = (lane & 3) << 1;
    #pragma unroll
    for (int mt = 0; mt < MTL; mt++) {
        int rA = mbase + mt * 16 + gr;
        int rB = rA + 8;
        bool okA = rA < rows, okB = rB < rows;
        float dA = okA ? g_dis[row0 + rA] : 0.f;
        float dB = okB ? g_dis[row0 + rB] : 0.f;
        #pragma unroll
        for (int nt = 0; nt < NTL; nt++) {
            int col = nbase + nt * 8 + tc;
            if (okA)
                *(__half2*)(out + (size_t)(row0 + rA) * N + col) =
                    __floats2half2_rn(acc[mt][nt][0] * dA, acc[mt][nt][1] * dA);
            if (okB)
                *(__half2*)(out + (size_t)(row0 + rB) * N + col) =
                    __floats2half2_rn(acc[mt][nt][2] * dB, acc[mt][nt][3] * dB);
        }
    }
}

// ---------------- CSR aggregation: out = fp16(relu((h[n] + sum h[s]) * dis + b)) ----------------
template<int F, bool POOL>
__global__ void k_agg(const __half* __restrict__ h, const float* __restrict__ bias,
                      const int* __restrict__ batch, __half* __restrict__ out) {
    constexpr int LPE = F / 8;        // lanes per node (8 halves each)
    constexpr int NPW = 32 / LPE;
    int gw   = (blockIdx.x * 256 + threadIdx.x) >> 5;
    int lane = threadIdx.x & 31;
    int sub  = lane / LPE;
    int l    = lane % LPE;
    int node = gw * NPW + sub;
    if (node >= N_NODES) return;

    const uint4* hv = (const uint4*)h;

    float2 acc[4];
    {
        uint4 sv = __ldg(&hv[(size_t)node * LPE + l]);
        __half2* p = (__half2*)&sv;
        #pragma unroll
        for (int k = 0; k < 4; k++) acc[k] = __half22float2(p[k]);
    }

    int rs = g_rowstart[node];
    int re = rs + g_degi[node];

    int j = rs;
    for (; j + 8 <= re; j += 8) {
        int4 ia = *(const int4*)(g_csr + j);
        int4 ib = *(const int4*)(g_csr + j + 4);
        uint4 v0 = __ldg(&hv[(size_t)ia.x * LPE + l]);
        uint4 v1 = __ldg(&hv[(size_t)ia.y * LPE + l]);
        uint4 v2 = __ldg(&hv[(size_t)ia.z * LPE + l]);
        uint4 v3 = __ldg(&hv[(size_t)ia.w * LPE + l]);
        uint4 v4 = __ldg(&hv[(size_t)ib.x * LPE + l]);
        uint4 v5 = __ldg(&hv[(size_t)ib.y * LPE + l]);
        uint4 v6 = __ldg(&hv[(size_t)ib.z * LPE + l]);
        uint4 v7 = __ldg(&hv[(size_t)ib.w * LPE + l]);
        acc_add(acc, v0); acc_add(acc, v1); acc_add(acc, v2); acc_add(acc, v3);
        acc_add(acc, v4); acc_add(acc, v5); acc_add(acc, v6); acc_add(acc, v7);
    }
    if (j + 4 <= re) {
        int4 ia = *(const int4*)(g_csr + j);
        uint4 v0 = __ldg(&hv[(size_t)ia.x * LPE + l]);
        uint4 v1 = __ldg(&hv[(size_t)ia.y * LPE + l]);
        uint4 v2 = __ldg(&hv[(size_t)ia.z * LPE + l]);
        uint4 v3 = __ldg(&hv[(size_t)ia.w * LPE + l]);
        acc_add(acc, v0); acc_add(acc, v1); acc_add(acc, v2); acc_add(acc, v3);
        j += 4;
    }
    for (; j < re; j++) {
        uint4 a = __ldg(&hv[(size_t)g_csr[j] * LPE + l]);
        acc_add(acc, a);
    }

    float dr = g_dis[node];
    float4 b0 = ((const float4*)bias)[l * 2];
    float4 b1 = ((const float4*)bias)[l * 2 + 1];
    float4 v0 = make_float4(fmaxf(fmaf(acc[0].x, dr, b0.x), 0.f),
                            fmaxf(fmaf(acc[0].y, dr, b0.y), 0.f),
                            fmaxf(fmaf(acc[1].x, dr, b0.z), 0.f),
                            fmaxf(fmaf(acc[1].y, dr, b0.w), 0.f));
    float4 v1 = make_float4(fmaxf(fmaf(acc[2].x, dr, b1.x), 0.f),
                            fmaxf(fmaf(acc[2].y, dr, b1.y), 0.f),
                            fmaxf(fmaf(acc[3].x, dr, b1.z), 0.f),
                            fmaxf(fmaf(acc[3].y, dr, b1.w), 0.f));
    if (POOL) {
        int g = batch[node];
        red_add_v4(g_pooled + g * 32 + l * 8, v0);
        red_add_v4(g_pooled + g * 32 + l * 8 + 4, v1);
    } else {
        uint4 o;
        o.x = h2_bits(__floats2half2_rn(v0.x, v0.y));
        o.y = h2_bits(__floats2half2_rn(v0.z, v0.w));
        o.z = h2_bits(__floats2half2_rn(v1.x, v1.y));
        o.w = h2_bits(__floats2half2_rn(v1.z, v1.w));
        ((uint4*)out)[(size_t)node * LPE + l] = o;
    }
}

// ---------------- head: out = (pooled/cnt) @ Wl + bl ----------------
__global__ void k_final(const float* __restrict__ Wl, const float* __restrict__ bl,
                        float* __restrict__ out) {
    int g = blockIdx.x;
    __shared__ float p[32];
    int tid = threadIdx.x;
    if (tid < 32) {
        float c = fmaxf(g_cnt[g], 1.0f);
        p[tid] = g_pooled[g * 32 + tid] / c;
    }
    __syncthreads();
    for (int j = tid; j < 768; j += 256) {
        float acc = bl[j];
        #pragma unroll
        for (int k = 0; k < 32; k++)
            acc = fmaf(p[k], Wl[k * 768 + j], acc);
        out[g * 768 + j] = acc;
    }
}

// ---------------- launch ----------------
extern "C" void kernel_launch(void* const* d_in, const int* in_sizes, int n_in,
                              void* d_out, int out_size) {
    const float* x  = (const float*)d_in[0];
    const float* W1 = (const float*)d_in[1];
    const float* b1 = (const float*)d_in[2];
    const float* W2 = (const float*)d_in[3];
    const float* b2 = (const float*)d_in[4];
    const float* W3 = (const float*)d_in[5];
    const float* b3 = (const float*)d_in[6];
    const float* Wl = (const float*)d_in[7];
    const float* bl = (const float*)d_in[8];
    const int* ei    = (const int*)d_in[9];
    const int* batch = (const int*)d_in[10];
    float* out = (float*)d_out;

    __half *p_w1h, *p_w2h, *p_w3h, *p_h1, *p_x2, *p_h2, *p_x3, *p_h3;
    cudaGetSymbolAddress((void**)&p_w1h, g_w1h);
    cudaGetSymbolAddress((void**)&p_w2h, g_w2h);
    cudaGetSymbolAddress((void**)&p_w3h, g_w3h);
    cudaGetSymbolAddress((void**)&p_h1,  g_h1);
    cudaGetSymbolAddress((void**)&p_x2,  g_x2);
    cudaGetSymbolAddress((void**)&p_h2,  g_h2);
    cudaGetSymbolAddress((void**)&p_x3,  g_x3);
    cudaGetSymbolAddress((void**)&p_h3,  g_h3);

    // smem: (MT*(K+8) + K*(N+8)) * 2 bytes
    int s1 = (128 * 136 + 128 * 136) * 2;   // 69632
    int s2 = (128 * 136 + 128 * 72) * 2;    // 53248
    int s3 = (128 * 72 + 64 * 40) * 2;      // 23552
    cudaFuncSetAttribute(k_hgemm<128, 128, 8, 2, 512, float, __half>,
                         cudaFuncAttributeMaxDynamicSharedMemorySize, s1);
    cudaFuncSetAttribute(k_hgemm<128, 64, 8, 2, 512, __half, __half>,
                         cudaFuncAttributeMaxDynamicSharedMemorySize, s2);
    cudaFuncSetAttribute(k_hgemm<64, 32, 8, 1, 256, __half, __half>,
                         cudaFuncAttributeMaxDynamicSharedMemorySize, s3);

    int mblocks = (N_NODES + 127) / 128;    // 313

    // ---- prep (W fp16 convert folded into k_zero) ----
    k_zero <<<NB, 256>>>(W1, W2, W3);
    k_count<<<625, 256>>>(ei, batch);
    k_scan <<<NB, 256>>>();

    // ---- layer 1: 128 -> 128 (launch #4 = gemm1, profiled) ----
    k_hgemm<128, 128, 8, 2, 512, float, __half><<<mblocks, 512, s1>>>(x, p_w1h, p_h1);
    k_fill <<<625, 256>>>(ei);
    k_agg<128, false><<<2500, 256>>>(p_h1, b1, batch, p_x2);

    // ---- layer 2: 128 -> 64 ----
    k_hgemm<128, 64, 8, 2, 512, __half, __half><<<mblocks, 512, s2>>>(p_x2, p_w2h, p_h2);
    k_agg<64, false><<<1250, 256>>>(p_h2, b2, batch, p_x3);

    // ---- layer 3: 64 -> 32 (pool fused) ----
    k_hgemm<64, 32, 8, 1, 256, __half, __half><<<mblocks, 256, s3>>>(p_x3, p_w3h, p_h3);
    k_agg<32, true><<<625, 256>>>(p_h3, b3, batch, nullptr);

    // ---- head ----
    k_final<<<N_GRAPHS, 256>>>(Wl, bl, out);
}

// round 14
// speedup vs baseline: 2.2799x; 1.0435x over previous
#include <cuda_runtime.h>
#include <cuda_fp16.h>
#include <cstdint>

#define N_NODES  40000
#define N_EDGES  640000
#define N_GRAPHS 256
#define NB 157            // ceil(40000/256) scan blocks
#define CSR_CAP 760000    // N_EDGES + N_NODES*3 worst-case pad-to-4
#define GEMM1_BLOCKS 313  // ceil(40000/128)
#define FILL_BLOCKS 313   // ceil(160000/512)

// ---------------- scratch (static __device__, no allocation) ----------------
__device__ __align__(16) int    g_degi[N_NODES];
__device__ __align__(16) int    g_rowstart[N_NODES];
__device__ __align__(16) int    g_cursor[N_NODES];
__device__ __align__(16) int    g_csr[CSR_CAP];
__device__ int    g_base;
__device__ __align__(16) float  g_dis[N_NODES];
__device__ __align__(16) __half g_w1h[128 * 128];
__device__ __align__(16) __half g_w2h[128 * 64];
__device__ __align__(16) __half g_w3h[64 * 32];
__device__ __align__(16) __half g_h1[N_NODES * 128];
__device__ __align__(16) __half g_x2[N_NODES * 128];
__device__ __align__(16) __half g_h2[N_NODES * 64];
__device__ __align__(16) __half g_x3[N_NODES * 64];
__device__ __align__(16) __half g_h3[N_NODES * 32];
__device__ __align__(16) float  g_pooled[N_GRAPHS * 32];
__device__ __align__(16) float  g_cnt[N_GRAPHS];

// ---------------- helpers ----------------
__device__ __forceinline__ void red_add_v4(float* addr, float4 v) {
    asm volatile("red.global.add.v4.f32 [%0], {%1, %2, %3, %4};"
                 :: "l"(addr), "f"(v.x), "f"(v.y), "f"(v.z), "f"(v.w)
                 : "memory");
}
__device__ __forceinline__ unsigned h2_bits(__half2 h) {
    unsigned u;
    *(__half2*)&u = h;
    return u;
}
__device__ __forceinline__ uint4 cvt8(float4 a, float4 b) {
    uint4 o;
    o.x = h2_bits(__floats2half2_rn(a.x, a.y));
    o.y = h2_bits(__floats2half2_rn(a.z, a.w));
    o.z = h2_bits(__floats2half2_rn(b.x, b.y));
    o.w = h2_bits(__floats2half2_rn(b.z, b.w));
    return o;
}
__device__ __forceinline__ void acc_add(float2 acc[4], uint4 v) {
    __half2* p = (__half2*)&v;
    #pragma unroll
    for (int k = 0; k < 4; k++) {
        float2 f = __half22float2(p[k]);
        acc[k].x += f.x; acc[k].y += f.y;
    }
}
__device__ __forceinline__ void ldsm_x4(unsigned* r, const __half* p) {
    unsigned a = (unsigned)__cvta_generic_to_shared(p);
    asm volatile("ldmatrix.sync.aligned.m8n8.x4.shared.b16 {%0,%1,%2,%3}, [%4];"
                 : "=r"(r[0]), "=r"(r[1]), "=r"(r[2]), "=r"(r[3]) : "r"(a));
}
__device__ __forceinline__ void ldsm_x4_t(unsigned* r, const __half* p) {
    unsigned a = (unsigned)__cvta_generic_to_shared(p);
    asm volatile("ldmatrix.sync.aligned.m8n8.x4.trans.shared.b16 {%0,%1,%2,%3}, [%4];"
                 : "=r"(r[0]), "=r"(r[1]), "=r"(r[2]), "=r"(r[3]) : "r"(a));
}
__device__ __forceinline__ void mma16816(float* d, const unsigned* a, const unsigned* b) {
    asm volatile(
        "mma.sync.aligned.m16n8k16.row.col.f32.f16.f16.f32 "
        "{%0,%1,%2,%3}, {%4,%5,%6,%7}, {%8,%9}, {%0,%1,%2,%3};"
        : "+f"(d[0]), "+f"(d[1]), "+f"(d[2]), "+f"(d[3])
        : "r"(a[0]), "r"(a[1]), "r"(a[2]), "r"(a[3]), "r"(b[0]), "r"(b[1]));
}

// ---------------- prep ----------------
// zero scratch + convert all three W matrices to fp16 (no extra launch)
__global__ void k_zero(const float* __restrict__ W1, const float* __restrict__ W2,
                       const float* __restrict__ W3) {
    int i = blockIdx.x * blockDim.x + threadIdx.x;
    if (i < N_NODES) g_degi[i] = 0;
    if (i < N_GRAPHS * 32) g_pooled[i] = 0.f;
    if (i < N_GRAPHS) g_cnt[i] = 0.f;
    if (i == 0) g_base = 0;
    if (i < 8192)
        ((__half2*)g_w1h)[i] = __float22half2_rn(((const float2*)W1)[i]);
    else if (i < 12288)
        ((__half2*)g_w2h)[i - 8192] = __float22half2_rn(((const float2*)W2)[i - 8192]);
    else if (i < 13312)
        ((__half2*)g_w3h)[i - 12288] = __float22half2_rn(((const float2*)W3)[i - 12288]);
}

// 4 edges per thread (int4 index loads); grid 625*256 = 160000 = N_EDGES/4
__global__ void k_count(const int* __restrict__ ei, const int* __restrict__ batch) {
    int i = blockIdx.x * blockDim.x + threadIdx.x;
    int4 d4 = ((const int4*)(ei + N_EDGES))[i];
    atomicAdd(&g_degi[d4.x], 1);
    atomicAdd(&g_degi[d4.y], 1);
    atomicAdd(&g_degi[d4.z], 1);
    atomicAdd(&g_degi[d4.w], 1);
    if (i < N_NODES) atomicAdd(&g_cnt[batch[i]], 1.0f);
}

// single-kernel scan over PADDED degrees (segments rounded to 4 ints)
__global__ void k_scan() {
    int t = threadIdx.x, i = blockIdx.x * 256 + t;
    int lane = t & 31, w = t >> 5;
    int v  = (i < N_NODES) ? g_degi[i] : 0;
    int pv = (v + 3) & ~3;

    int sv = pv;
    #pragma unroll
    for (int off = 1; off < 32; off <<= 1) {
        int n = __shfl_up_sync(0xffffffffu, sv, off);
        if (lane >= off) sv += n;
    }
    __shared__ int ws[8];
    if (lane == 31) ws[w] = sv;
    __syncthreads();
    if (w == 0 && lane < 8) {
        int x = ws[lane];
        #pragma unroll
        for (int off = 1; off < 8; off <<= 1) {
            int n = __shfl_up_sync(0xffu, x, off);
            if (lane >= off) x += n;
        }
        ws[lane] = x;
    }
    __syncthreads();
    int incl = sv + (w ? ws[w - 1] : 0);

    __shared__ int base;
    if (t == 255) base = atomicAdd(&g_base, incl);
    __syncthreads();

    if (i < N_NODES) {
        int ex = base + incl - pv;
        g_rowstart[i] = ex;
        g_cursor[i]   = ex;
        g_dis[i]      = rsqrtf((float)v + 1.0f);
    }
}

// ---------------- GEMM body (shared by k_hgemm and the merged k_l1) ----------
// computes tile `tile` of: out = fp16((in @ W) * dis[row])
template<int K, int N, int WM, int WN, int THREADS, typename TIN, typename TW>
__device__ __forceinline__ void gemm_body(const TIN* __restrict__ in,
                                          const TW* __restrict__ W,
                                          __half* __restrict__ out,
                                          int tile, __half* sm) {
    constexpr int MT  = 128;
    constexpr int XS  = K + 8;
    constexpr int WS  = N + 8;
    constexpr int MW  = MT / WM;
    constexpr int NW  = N / WN;
    constexpr int MTL = MW / 16;
    constexpr int NTL = NW / 8;
    static_assert(WM * WN == THREADS / 32, "warp layout");
    static_assert(MTL >= 1 && NTL >= 2 && NTL % 2 == 0, "tile shape");

    __half* Xs = sm;                 // MT x XS
    __half* Ws = sm + MT * XS;       // K x WS

    int tid  = threadIdx.x;
    int row0 = tile * MT;
    int rows = N_NODES - row0; if (rows > MT) rows = MT;

    // X tile first (DRAM long pole), then W (L2-resident)
    for (int i = tid; i < MT * (K / 8); i += THREADS) {
        int r = i / (K / 8), c = i % (K / 8);
        uint4 v = make_uint4(0, 0, 0, 0);
        if (r < rows) {
            if (sizeof(TIN) == 4) {
                const float4* src = (const float4*)in;
                float4 a = src[((size_t)(row0 + r) * (K / 8) + c) * 2];
                float4 b = src[((size_t)(row0 + r) * (K / 8) + c) * 2 + 1];
                v = cvt8(a, b);
            } else {
                v = ((const uint4*)in)[(size_t)(row0 + r) * (K / 8) + c];
            }
        }
        *(uint4*)(Xs + r * XS + c * 8) = v;
    }
    for (int i = tid; i < K * (N / 8); i += THREADS) {
        int k = i / (N / 8), c = i % (N / 8);
        *(uint4*)(Ws + k * WS + c * 8) = ((const uint4*)W)[i];
    }
    __syncthreads();

    int wid = tid >> 5, lane = tid & 31;
    int wm = wid % WM, wn = wid / WM;
    int mbase = wm * MW, nbase = wn * NW;

    float acc[MTL][NTL][4];
    #pragma unroll
    for (int mt = 0; mt < MTL; mt++)
        #pragma unroll
        for (int nt = 0; nt < NTL; nt++)
            acc[mt][nt][0] = acc[mt][nt][1] = acc[mt][nt][2] = acc[mt][nt][3] = 0.f;

    #pragma unroll
    for (int k0 = 0; k0 < K; k0 += 16) {
        unsigned af[MTL][4];
        unsigned bf[NTL][2];
        #pragma unroll
        for (int mt = 0; mt < MTL; mt++) {
            const __half* p = Xs + (mbase + mt * 16 + (lane & 15)) * XS
                                 + k0 + ((lane >> 4) << 3);
            ldsm_x4(af[mt], p);
        }
        #pragma unroll
        for (int p2 = 0; p2 < NTL / 2; p2++) {
            const __half* p = Ws + (k0 + (lane & 15)) * WS
                                 + nbase + p2 * 16 + ((lane >> 4) << 3);
            ldsm_x4_t(&bf[p2 * 2][0], p);
        }
        #pragma unroll
        for (int mt = 0; mt < MTL; mt++)
            #pragma unroll
            for (int nt = 0; nt < NTL; nt++)
                mma16816(acc[mt][nt], af[mt], bf[nt]);
    }

    int gr = lane >> 2, tc = (lane & 3) << 1;
    #pragma unroll
    for (int mt = 0; mt < MTL; mt++) {
        int rA = mbase + mt * 16 + gr;
        int rB = rA + 8;
        bool okA = rA < rows, okB = rB < rows;
        float dA = okA ? g_dis[row0 + rA] : 0.f;
        float dB = okB ? g_dis[row0 + rB] : 0.f;
        #pragma unroll
        for (int nt = 0; nt < NTL; nt++) {
            int col = nbase + nt * 8 + tc;
            if (okA)
                *(__half2*)(out + (size_t)(row0 + rA) * N + col) =
                    __floats2half2_rn(acc[mt][nt][0] * dA, acc[mt][nt][1] * dA);
            if (okB)
                *(__half2*)(out + (size_t)(row0 + rB) * N + col) =
                    __floats2half2_rn(acc[mt][nt][2] * dB, acc[mt][nt][3] * dB);
        }
    }
}

// standalone GEMM (layers 2, 3)
template<int K, int N, int WM, int WN, int THREADS, typename TIN, typename TW>
__global__ void __launch_bounds__(THREADS, 2)
k_hgemm(const TIN* __restrict__ in, const TW* __restrict__ W,
        __half* __restrict__ out) {
    extern __shared__ __half sm[];
    gemm_body<K, N, WM, WN, THREADS, TIN, TW>(in, W, out, blockIdx.x, sm);
}

// merged layer-1 kernel: blocks [0, GEMM1_BLOCKS) do gemm1, rest do CSR fill.
// gemm1 (DRAM-latency-bound) and fill (L2-atomic-bound) overlap in one wave-set.
__global__ void __launch_bounds__(512, 2)
k_l1(const float* __restrict__ x, const __half* __restrict__ W,
     __half* __restrict__ out, const int* __restrict__ ei) {
    extern __shared__ __half sm[];
    if (blockIdx.x < GEMM1_BLOCKS) {
        gemm_body<128, 128, 8, 2, 512, float, __half>(x, W, out, blockIdx.x, sm);
    } else {
        int i = (blockIdx.x - GEMM1_BLOCKS) * 512 + threadIdx.x;
        if (i < N_EDGES / 4) {
            int4 s4 = ((const int4*)ei)[i];
            int4 d4 = ((const int4*)(ei + N_EDGES))[i];
            g_csr[atomicAdd(&g_cursor[d4.x], 1)] = s4.x;
            g_csr[atomicAdd(&g_cursor[d4.y], 1)] = s4.y;
            g_csr[atomicAdd(&g_cursor[d4.z], 1)] = s4.z;
            g_csr[atomicAdd(&g_cursor[d4.w], 1)] = s4.w;
        }
    }
}

// ---------------- CSR aggregation: out = fp16(relu((h[n] + sum h[s]) * dis + b)) ----------------
template<int F, bool POOL>
__global__ void k_agg(const __half* __restrict__ h, const float* __restrict__ bias,
                      const int* __restrict__ batch, __half* __restrict__ out) {
    constexpr int LPE = F / 8;        // lanes per node (8 halves each)
    constexpr int NPW = 32 / LPE;
    int gw   = (blockIdx.x * 256 + threadIdx.x) >> 5;
    int lane = threadIdx.x & 31;
    int sub  = lane / LPE;
    int l    = lane % LPE;
    int node = gw * NPW + sub;
    if (node >= N_NODES) return;

    const uint4* hv = (const uint4*)h;

    float2 acc[4];
    {
        uint4 sv = __ldg(&hv[(size_t)node * LPE + l]);
        __half2* p = (__half2*)&sv;
        #pragma unroll
        for (int k = 0; k < 4; k++) acc[k] = __half22float2(p[k]);
    }

    int rs = g_rowstart[node];
    int re = rs + g_degi[node];

    int j = rs;
    for (; j + 8 <= re; j += 8) {
        int4 ia = *(const int4*)(g_csr + j);
        int4 ib = *(const int4*)(g_csr + j + 4);
        uint4 v0 = __ldg(&hv[(size_t)ia.x * LPE + l]);
        uint4 v1 = __ldg(&hv[(size_t)ia.y * LPE + l]);
        uint4 v2 = __ldg(&hv[(size_t)ia.z * LPE + l]);
        uint4 v3 = __ldg(&hv[(size_t)ia.w * LPE + l]);
        uint4 v4 = __ldg(&hv[(size_t)ib.x * LPE + l]);
        uint4 v5 = __ldg(&hv[(size_t)ib.y * LPE + l]);
        uint4 v6 = __ldg(&hv[(size_t)ib.z * LPE + l]);
        uint4 v7 = __ldg(&hv[(size_t)ib.w * LPE + l]);
        acc_add(acc, v0); acc_add(acc, v1); acc_add(acc, v2); acc_add(acc, v3);
        acc_add(acc, v4); acc_add(acc, v5); acc_add(acc, v6); acc_add(acc, v7);
    }
    if (j + 4 <= re) {
        int4 ia = *(const int4*)(g_csr + j);
        uint4 v0 = __ldg(&hv[(size_t)ia.x * LPE + l]);
        uint4 v1 = __ldg(&hv[(size_t)ia.y * LPE + l]);
        uint4 v2 = __ldg(&hv[(size_t)ia.z * LPE + l]);
        uint4 v3 = __ldg(&hv[(size_t)ia.w * LPE + l]);
        acc_add(acc, v0); acc_add(acc, v1); acc_add(acc, v2); acc_add(acc, v3);
        j += 4;
    }
    for (; j < re; j++) {
        uint4 a = __ldg(&hv[(size_t)g_csr[j] * LPE + l]);
        acc_add(acc, a);
    }

    float dr = g_dis[node];
    float4 b0 = ((const float4*)bias)[l * 2];
    float4 b1 = ((const float4*)bias)[l * 2 + 1];
    float4 v0 = make_float4(fmaxf(fmaf(acc[0].x, dr, b0.x), 0.f),
                            fmaxf(fmaf(acc[0].y, dr, b0.y), 0.f),
                            fmaxf(fmaf(acc[1].x, dr, b0.z), 0.f),
                            fmaxf(fmaf(acc[1].y, dr, b0.w), 0.f));
    float4 v1 = make_float4(fmaxf(fmaf(acc[2].x, dr, b1.x), 0.f),
                            fmaxf(fmaf(acc[2].y, dr, b1.y), 0.f),
                            fmaxf(fmaf(acc[3].x, dr, b1.z), 0.f),
                            fmaxf(fmaf(acc[3].y, dr, b1.w), 0.f));
    if (POOL) {
        int g = batch[node];
        red_add_v4(g_pooled + g * 32 + l * 8, v0);
        red_add_v4(g_pooled + g * 32 + l * 8 + 4, v1);
    } else {
        uint4 o;
        o.x = h2_bits(__floats2half2_rn(v0.x, v0.y));
        o.y = h2_bits(__floats2half2_rn(v0.z, v0.w));
        o.z = h2_bits(__floats2half2_rn(v1.x, v1.y));
        o.w = h2_bits(__floats2half2_rn(v1.z, v1.w));
        ((uint4*)out)[(size_t)node * LPE + l] = o;
    }
}

// ---------------- head: out = (pooled/cnt) @ Wl + bl ----------------
__global__ void k_final(const float* __restrict__ Wl, const float* __restrict__ bl,
                        float* __restrict__ out) {
    int g = blockIdx.x;
    __shared__ float p[32];
    int tid = threadIdx.x;
    if (tid < 32) {
        float c = fmaxf(g_cnt[g], 1.0f);
        p[tid] = g_pooled[g * 32 + tid] / c;
    }
    __syncthreads();
    for (int j = tid; j < 768; j += 256) {
        float acc = bl[j];
        #pragma unroll
        for (int k = 0; k < 32; k++)
            acc = fmaf(p[k], Wl[k * 768 + j], acc);
        out[g * 768 + j] = acc;
    }
}

// ---------------- launch ----------------
extern "C" void kernel_launch(void* const* d_in, const int* in_sizes, int n_in,
                              void* d_out, int out_size) {
    const float* x  = (const float*)d_in[0];
    const float* W1 = (const float*)d_in[1];
    const float* b1 = (const float*)d_in[2];
    const float* W2 = (const float*)d_in[3];
    const float* b2 = (const float*)d_in[4];
    const float* W3 = (const float*)d_in[5];
    const float* b3 = (const float*)d_in[6];
    const float* Wl = (const float*)d_in[7];
    const float* bl = (const float*)d_in[8];
    const int* ei    = (const int*)d_in[9];
    const int* batch = (const int*)d_in[10];
    float* out = (float*)d_out;

    __half *p_w1h, *p_w2h, *p_w3h, *p_h1, *p_x2, *p_h2, *p_x3, *p_h3;
    cudaGetSymbolAddress((void**)&p_w1h, g_w1h);
    cudaGetSymbolAddress((void**)&p_w2h, g_w2h);
    cudaGetSymbolAddress((void**)&p_w3h, g_w3h);
    cudaGetSymbolAddress((void**)&p_h1,  g_h1);
    cudaGetSymbolAddress((void**)&p_x2,  g_x2);
    cudaGetSymbolAddress((void**)&p_h2,  g_h2);
    cudaGetSymbolAddress((void**)&p_x3,  g_x3);
    cudaGetSymbolAddress((void**)&p_h3,  g_h3);

    // smem: (MT*(K+8) + K*(N+8)) * 2 bytes
    int s1 = (128 * 136 + 128 * 136) * 2;   // 69632
    int s2 = (128 * 136 + 128 * 72) * 2;    // 53248
    int s3 = (128 * 72 + 64 * 40) * 2;      // 23552
    cudaFuncSetAttribute(k_l1, cudaFuncAttributeMaxDynamicSharedMemorySize, s1);
    cudaFuncSetAttribute(k_hgemm<128, 64, 8, 2, 512, __half, __half>,
                         cudaFuncAttributeMaxDynamicSharedMemorySize, s2);
    cudaFuncSetAttribute(k_hgemm<64, 32, 8, 1, 256, __half, __half>,
                         cudaFuncAttributeMaxDynamicSharedMemorySize, s3);

    int mblocks = (N_NODES + 127) / 128;    // 313

    // ---- prep (W fp16 convert folded into k_zero) ----
    k_zero <<<NB, 256>>>(W1, W2, W3);
    k_count<<<625, 256>>>(ei, batch);
    k_scan <<<NB, 256>>>();

    // ---- layer 1: gemm1 + CSR fill merged (launch #4, profiled) ----
    k_l1<<<GEMM1_BLOCKS + FILL_BLOCKS, 512, s1>>>(x, p_w1h, p_h1, ei);
    k_agg<128, false><<<2500, 256>>>(p_h1, b1, batch, p_x2);

    // ---- layer 2: 128 -> 64 ----
    k_hgemm<128, 64, 8, 2, 512, __half, __half><<<mblocks, 512, s2>>>(p_x2, p_w2h, p_h2);
    k_agg<64, false><<<1250, 256>>>(p_h2, b2, batch, p_x3);

    // ---- layer 3: 64 -> 32 (pool fused) ----
    k_hgemm<64, 32, 8, 1, 256, __half, __half><<<mblocks, 256, s3>>>(p_x3, p_w3h, p_h3);
    k_agg<32, true><<<625, 256>>>(p_h3, b3, batch, nullptr);

    // ---- head ----
    k_final<<<N_GRAPHS, 256>>>(Wl, bl, out);
}

// round 15
// speedup vs baseline: 2.3103x; 1.0133x over previous
#include <cuda_runtime.h>
#include <cuda_fp16.h>
#include <cstdint>

#define N_NODES  40000
#define N_EDGES  640000
#define N_GRAPHS 256
#define NB 157            // ceil(40000/256) scan blocks
#define CSR_CAP 760000    // N_EDGES + N_NODES*3 worst-case pad-to-4
#define GEMM1_BLOCKS 313  // ceil(40000/128)
#define FILL_BLOCKS 313   // ceil(160000/512)

// ---------------- scratch (static __device__, no allocation) ----------------
__device__ __align__(16) int    g_degi[N_NODES];
__device__ __align__(16) int    g_rowstart[N_NODES];
__device__ __align__(16) int    g_cursor[N_NODES];
__device__ __align__(16) int    g_csr[CSR_CAP];
__device__ int    g_base;
__device__ __align__(16) float  g_dis[N_NODES];
__device__ __align__(16) __half g_w1h[128 * 128];
__device__ __align__(16) __half g_w2h[128 * 64];
__device__ __align__(16) __half g_w3h[64 * 32];
__device__ __align__(16) __half g_h1[N_NODES * 128];
__device__ __align__(16) __half g_x2[N_NODES * 128];
__device__ __align__(16) __half g_h2[N_NODES * 64];
__device__ __align__(16) __half g_x3[N_NODES * 64];
__device__ __align__(16) __half g_h3[N_NODES * 32];
__device__ __align__(16) float  g_pooled[N_GRAPHS * 32];
__device__ __align__(16) float  g_cnt[N_GRAPHS];

// ---------------- helpers ----------------
__device__ __forceinline__ void red_add_v4(float* addr, float4 v) {
    asm volatile("red.global.add.v4.f32 [%0], {%1, %2, %3, %4};"
                 :: "l"(addr), "f"(v.x), "f"(v.y), "f"(v.z), "f"(v.w)
                 : "memory");
}
__device__ __forceinline__ unsigned h2_bits(__half2 h) {
    unsigned u;
    *(__half2*)&u = h;
    return u;
}
__device__ __forceinline__ uint4 cvt8(float4 a, float4 b) {
    uint4 o;
    o.x = h2_bits(__floats2half2_rn(a.x, a.y));
    o.y = h2_bits(__floats2half2_rn(a.z, a.w));
    o.z = h2_bits(__floats2half2_rn(b.x, b.y));
    o.w = h2_bits(__floats2half2_rn(b.z, b.w));
    return o;
}
__device__ __forceinline__ void acc_add(float2 acc[4], uint4 v) {
    __half2* p = (__half2*)&v;
    #pragma unroll
    for (int k = 0; k < 4; k++) {
        float2 f = __half22float2(p[k]);
        acc[k].x += f.x; acc[k].y += f.y;
    }
}
__device__ __forceinline__ void ldsm_x4(unsigned* r, const __half* p) {
    unsigned a = (unsigned)__cvta_generic_to_shared(p);
    asm volatile("ldmatrix.sync.aligned.m8n8.x4.shared.b16 {%0,%1,%2,%3}, [%4];"
                 : "=r"(r[0]), "=r"(r[1]), "=r"(r[2]), "=r"(r[3]) : "r"(a));
}
__device__ __forceinline__ void ldsm_x4_t(unsigned* r, const __half* p) {
    unsigned a = (unsigned)__cvta_generic_to_shared(p);
    asm volatile("ldmatrix.sync.aligned.m8n8.x4.trans.shared.b16 {%0,%1,%2,%3}, [%4];"
                 : "=r"(r[0]), "=r"(r[1]), "=r"(r[2]), "=r"(r[3]) : "r"(a));
}
__device__ __forceinline__ void mma16816(float* d, const unsigned* a, const unsigned* b) {
    asm volatile(
        "mma.sync.aligned.m16n8k16.row.col.f32.f16.f16.f32 "
        "{%0,%1,%2,%3}, {%4,%5,%6,%7}, {%8,%9}, {%0,%1,%2,%3};"
        : "+f"(d[0]), "+f"(d[1]), "+f"(d[2]), "+f"(d[3])
        : "r"(a[0]), "r"(a[1]), "r"(a[2]), "r"(a[3]), "r"(b[0]), "r"(b[1]));
}

// ---------------- prep ----------------
// zero scratch + convert all three W matrices to fp16 (no extra launch)
__global__ void k_zero(const float* __restrict__ W1, const float* __restrict__ W2,
                       const float* __restrict__ W3) {
    int i = blockIdx.x * blockDim.x + threadIdx.x;
    if (i < N_NODES) g_degi[i] = 0;
    if (i < N_GRAPHS * 32) g_pooled[i] = 0.f;
    if (i < N_GRAPHS) g_cnt[i] = 0.f;
    if (i == 0) g_base = 0;
    if (i < 8192)
        ((__half2*)g_w1h)[i] = __float22half2_rn(((const float2*)W1)[i]);
    else if (i < 12288)
        ((__half2*)g_w2h)[i - 8192] = __float22half2_rn(((const float2*)W2)[i - 8192]);
    else if (i < 13312)
        ((__half2*)g_w3h)[i - 12288] = __float22half2_rn(((const float2*)W3)[i - 12288]);
}

// 4 edges per thread (int4 index loads); grid 625*256 = 160000 = N_EDGES/4
__global__ void k_count(const int* __restrict__ ei, const int* __restrict__ batch) {
    int i = blockIdx.x * blockDim.x + threadIdx.x;
    int4 d4 = ((const int4*)(ei + N_EDGES))[i];
    atomicAdd(&g_degi[d4.x], 1);
    atomicAdd(&g_degi[d4.y], 1);
    atomicAdd(&g_degi[d4.z], 1);
    atomicAdd(&g_degi[d4.w], 1);
    if (i < N_NODES) atomicAdd(&g_cnt[batch[i]], 1.0f);
}

// single-kernel scan over PADDED degrees (segments rounded to 4 ints)
__global__ void k_scan() {
    int t = threadIdx.x, i = blockIdx.x * 256 + t;
    int lane = t & 31, w = t >> 5;
    int v  = (i < N_NODES) ? g_degi[i] : 0;
    int pv = (v + 3) & ~3;

    int sv = pv;
    #pragma unroll
    for (int off = 1; off < 32; off <<= 1) {
        int n = __shfl_up_sync(0xffffffffu, sv, off);
        if (lane >= off) sv += n;
    }
    __shared__ int ws[8];
    if (lane == 31) ws[w] = sv;
    __syncthreads();
    if (w == 0 && lane < 8) {
        int x = ws[lane];
        #pragma unroll
        for (int off = 1; off < 8; off <<= 1) {
            int n = __shfl_up_sync(0xffu, x, off);
            if (lane >= off) x += n;
        }
        ws[lane] = x;
    }
    __syncthreads();
    int incl = sv + (w ? ws[w - 1] : 0);

    __shared__ int base;
    if (t == 255) base = atomicAdd(&g_base, incl);
    __syncthreads();

    if (i < N_NODES) {
        int ex = base + incl - pv;
        g_rowstart[i] = ex;
        g_cursor[i]   = ex;
        g_dis[i]      = rsqrtf((float)v + 1.0f);
    }
}

// ---------------- GEMM body (shared by k_hgemm and the merged k_l1) ----------
// computes tile `tile` of: out = fp16((in @ W) * dis[row])
// staging loaders are two-phase (batched LDG burst, then convert+STS) for MLP.
template<int K, int N, int WM, int WN, int THREADS, typename TIN, typename TW>
__device__ __forceinline__ void gemm_body(const TIN* __restrict__ in,
                                          const TW* __restrict__ W,
                                          __half* __restrict__ out,
                                          int tile, __half* sm) {
    constexpr int MT  = 128;
    constexpr int XS  = K + 8;
    constexpr int WS  = N + 8;
    constexpr int MW  = MT / WM;
    constexpr int NW  = N / WN;
    constexpr int MTL = MW / 16;
    constexpr int NTL = NW / 8;
    constexpr int XLD = MT * (K / 8) / THREADS;   // uint4 stores per thread
    constexpr int WLD = K * (N / 8) / THREADS;
    static_assert(WM * WN == THREADS / 32, "warp layout");
    static_assert(MTL >= 1 && NTL >= 2 && NTL % 2 == 0, "tile shape");
    static_assert(MT * (K / 8) % THREADS == 0 && K * (N / 8) % THREADS == 0, "ld");

    __half* Xs = sm;                 // MT x XS
    __half* Ws = sm + MT * XS;       // K x WS

    int tid  = threadIdx.x;
    int row0 = tile * MT;
    int rows = N_NODES - row0; if (rows > MT) rows = MT;

    // ---- phase 1: issue ALL X + W global loads (front-batched, high MLP) ----
    uint4 xv[XLD];
    if (sizeof(TIN) == 4) {
        float4 xa[XLD], xb[XLD];
        #pragma unroll
        for (int j = 0; j < XLD; j++) {
            int i = tid + j * THREADS;
            int r = i / (K / 8), c = i % (K / 8);
            xa[j] = make_float4(0, 0, 0, 0);
            xb[j] = xa[j];
            if (r < rows) {
                const float4* src = (const float4*)in;
                size_t base = ((size_t)(row0 + r) * (K / 8) + c) * 2;
                xa[j] = src[base];
                xb[j] = src[base + 1];
            }
        }
        #pragma unroll
        for (int j = 0; j < XLD; j++) xv[j] = cvt8(xa[j], xb[j]);
    } else {
        #pragma unroll
        for (int j = 0; j < XLD; j++) {
            int i = tid + j * THREADS;
            int r = i / (K / 8);
            xv[j] = make_uint4(0, 0, 0, 0);
            if (r < rows)
                xv[j] = ((const uint4*)in)[(size_t)row0 * (K / 8) + i];
        }
    }
    uint4 wv[WLD];
    #pragma unroll
    for (int j = 0; j < WLD; j++)
        wv[j] = ((const uint4*)W)[tid + j * THREADS];

    // ---- phase 2: stores to smem ----
    #pragma unroll
    for (int j = 0; j < XLD; j++) {
        int i = tid + j * THREADS;
        int r = i / (K / 8), c = i % (K / 8);
        *(uint4*)(Xs + r * XS + c * 8) = xv[j];
    }
    #pragma unroll
    for (int j = 0; j < WLD; j++) {
        int i = tid + j * THREADS;
        int k = i / (N / 8), c = i % (N / 8);
        *(uint4*)(Ws + k * WS + c * 8) = wv[j];
    }
    __syncthreads();

    int wid = tid >> 5, lane = tid & 31;
    int wm = wid % WM, wn = wid / WM;
    int mbase = wm * MW, nbase = wn * NW;

    float acc[MTL][NTL][4];
    #pragma unroll
    for (int mt = 0; mt < MTL; mt++)
        #pragma unroll
        for (int nt = 0; nt < NTL; nt++)
            acc[mt][nt][0] = acc[mt][nt][1] = acc[mt][nt][2] = acc[mt][nt][3] = 0.f;

    #pragma unroll
    for (int k0 = 0; k0 < K; k0 += 16) {
        unsigned af[MTL][4];
        unsigned bf[NTL][2];
        #pragma unroll
        for (int mt = 0; mt < MTL; mt++) {
            const __half* p = Xs + (mbase + mt * 16 + (lane & 15)) * XS
                                 + k0 + ((lane >> 4) << 3);
            ldsm_x4(af[mt], p);
        }
        #pragma unroll
        for (int p2 = 0; p2 < NTL / 2; p2++) {
            const __half* p = Ws + (k0 + (lane & 15)) * WS
                                 + nbase + p2 * 16 + ((lane >> 4) << 3);
            ldsm_x4_t(&bf[p2 * 2][0], p);
        }
        #pragma unroll
        for (int mt = 0; mt < MTL; mt++)
            #pragma unroll
            for (int nt = 0; nt < NTL; nt++)
                mma16816(acc[mt][nt], af[mt], bf[nt]);
    }

    int gr = lane >> 2, tc = (lane & 3) << 1;
    #pragma unroll
    for (int mt = 0; mt < MTL; mt++) {
        int rA = mbase + mt * 16 + gr;
        int rB = rA + 8;
        bool okA = rA < rows, okB = rB < rows;
        float dA = okA ? g_dis[row0 + rA] : 0.f;
        float dB = okB ? g_dis[row0 + rB] : 0.f;
        #pragma unroll
        for (int nt = 0; nt < NTL; nt++) {
            int col = nbase + nt * 8 + tc;
            if (okA)
                *(__half2*)(out + (size_t)(row0 + rA) * N + col) =
                    __floats2half2_rn(acc[mt][nt][0] * dA, acc[mt][nt][1] * dA);
            if (okB)
                *(__half2*)(out + (size_t)(row0 + rB) * N + col) =
                    __floats2half2_rn(acc[mt][nt][2] * dB, acc[mt][nt][3] * dB);
        }
    }
}

// standalone GEMM (layers 2, 3)
template<int K, int N, int WM, int WN, int THREADS, typename TIN, typename TW>
__global__ void __launch_bounds__(THREADS, 2)
k_hgemm(const TIN* __restrict__ in, const TW* __restrict__ W,
        __half* __restrict__ out) {
    extern __shared__ __half sm[];
    gemm_body<K, N, WM, WN, THREADS, TIN, TW>(in, W, out, blockIdx.x, sm);
}

// merged layer-1 kernel: blocks [0, GEMM1_BLOCKS) do gemm1, rest do CSR fill.
__global__ void __launch_bounds__(512, 2)
k_l1(const float* __restrict__ x, const __half* __restrict__ W,
     __half* __restrict__ out, const int* __restrict__ ei) {
    extern __shared__ __half sm[];
    if (blockIdx.x < GEMM1_BLOCKS) {
        gemm_body<128, 128, 8, 2, 512, float, __half>(x, W, out, blockIdx.x, sm);
    } else {
        int i = (blockIdx.x - GEMM1_BLOCKS) * 512 + threadIdx.x;
        if (i < N_EDGES / 4) {
            int4 s4 = ((const int4*)ei)[i];
            int4 d4 = ((const int4*)(ei + N_EDGES))[i];
            g_csr[atomicAdd(&g_cursor[d4.x], 1)] = s4.x;
            g_csr[atomicAdd(&g_cursor[d4.y], 1)] = s4.y;
            g_csr[atomicAdd(&g_cursor[d4.z], 1)] = s4.z;
            g_csr[atomicAdd(&g_cursor[d4.w], 1)] = s4.w;
        }
    }
}

// ---------------- CSR aggregation: out = fp16(relu((h[n] + sum h[s]) * dis + b)) ----------------
template<int F, bool POOL>
__global__ void k_agg(const __half* __restrict__ h, const float* __restrict__ bias,
                      const int* __restrict__ batch, __half* __restrict__ out) {
    constexpr int LPE = F / 8;        // lanes per node (8 halves each)
    constexpr int NPW = 32 / LPE;
    int gw   = (blockIdx.x * 256 + threadIdx.x) >> 5;
    int lane = threadIdx.x & 31;
    int sub  = lane / LPE;
    int l    = lane % LPE;
    int node = gw * NPW + sub;
    if (node >= N_NODES) return;

    const uint4* hv = (const uint4*)h;

    float2 acc[4];
    {
        uint4 sv = __ldg(&hv[(size_t)node * LPE + l]);
        __half2* p = (__half2*)&sv;
        #pragma unroll
        for (int k = 0; k < 4; k++) acc[k] = __half22float2(p[k]);
    }

    int rs = g_rowstart[node];
    int re = rs + g_degi[node];

    int j = rs;
    for (; j + 8 <= re; j += 8) {
        int4 ia = *(const int4*)(g_csr + j);
        int4 ib = *(const int4*)(g_csr + j + 4);
        uint4 v0 = __ldg(&hv[(size_t)ia.x * LPE + l]);
        uint4 v1 = __ldg(&hv[(size_t)ia.y * LPE + l]);
        uint4 v2 = __ldg(&hv[(size_t)ia.z * LPE + l]);
        uint4 v3 = __ldg(&hv[(size_t)ia.w * LPE + l]);
        uint4 v4 = __ldg(&hv[(size_t)ib.x * LPE + l]);
        uint4 v5 = __ldg(&hv[(size_t)ib.y * LPE + l]);
        uint4 v6 = __ldg(&hv[(size_t)ib.z * LPE + l]);
        uint4 v7 = __ldg(&hv[(size_t)ib.w * LPE + l]);
        acc_add(acc, v0); acc_add(acc, v1); acc_add(acc, v2); acc_add(acc, v3);
        acc_add(acc, v4); acc_add(acc, v5); acc_add(acc, v6); acc_add(acc, v7);
    }
    if (j + 4 <= re) {
        int4 ia = *(const int4*)(g_csr + j);
        uint4 v0 = __ldg(&hv[(size_t)ia.x * LPE + l]);
        uint4 v1 = __ldg(&hv[(size_t)ia.y * LPE + l]);
        uint4 v2 = __ldg(&hv[(size_t)ia.z * LPE + l]);
        uint4 v3 = __ldg(&hv[(size_t)ia.w * LPE + l]);
        acc_add(acc, v0); acc_add(acc, v1); acc_add(acc, v2); acc_add(acc, v3);
        j += 4;
    }
    for (; j < re; j++) {
        uint4 a = __ldg(&hv[(size_t)g_csr[j] * LPE + l]);
        acc_add(acc, a);
    }

    float dr = g_dis[node];
    float4 b0 = ((const float4*)bias)[l * 2];
    float4 b1 = ((const float4*)bias)[l * 2 + 1];
    float4 v0 = make_float4(fmaxf(fmaf(acc[0].x, dr, b0.x), 0.f),
                            fmaxf(fmaf(acc[0].y, dr, b0.y), 0.f),
                            fmaxf(fmaf(acc[1].x, dr, b0.z), 0.f),
                            fmaxf(fmaf(acc[1].y, dr, b0.w), 0.f));
    float4 v1 = make_float4(fmaxf(fmaf(acc[2].x, dr, b1.x), 0.f),
                            fmaxf(fmaf(acc[2].y, dr, b1.y), 0.f),
                            fmaxf(fmaf(acc[3].x, dr, b1.z), 0.f),
                            fmaxf(fmaf(acc[3].y, dr, b1.w), 0.f));
    if (POOL) {
        int g = batch[node];
        red_add_v4(g_pooled + g * 32 + l * 8, v0);
        red_add_v4(g_pooled + g * 32 + l * 8 + 4, v1);
    } else {
        uint4 o;
        o.x = h2_bits(__floats2half2_rn(v0.x, v0.y));
        o.y = h2_bits(__floats2half2_rn(v0.z, v0.w));
        o.z = h2_bits(__floats2half2_rn(v1.x, v1.y));
        o.w = h2_bits(__floats2half2_rn(v1.z, v1.w));
        ((uint4*)out)[(size_t)node * LPE + l] = o;
    }
}

// ---------------- head: out = (pooled/cnt) @ Wl + bl ----------------
__global__ void k_final(const float* __restrict__ Wl, const float* __restrict__ bl,
                        float* __restrict__ out) {
    int g = blockIdx.x;
    __shared__ float p[32];
    int tid = threadIdx.x;
    if (tid < 32) {
        float c = fmaxf(g_cnt[g], 1.0f);
        p[tid] = g_pooled[g * 32 + tid] / c;
    }
    __syncthreads();
    for (int j = tid; j < 768; j += 256) {
        float acc = bl[j];
        #pragma unroll
        for (int k = 0; k < 32; k++)
            acc = fmaf(p[k], Wl[k * 768 + j], acc);
        out[g * 768 + j] = acc;
    }
}

// ---------------- launch ----------------
extern "C" void kernel_launch(void* const* d_in, const int* in_sizes, int n_in,
                              void* d_out, int out_size) {
    const float* x  = (const float*)d_in[0];
    const float* W1 = (const float*)d_in[1];
    const float* b1 = (const float*)d_in[2];
    const float* W2 = (const float*)d_in[3];
    const float* b2 = (const float*)d_in[4];
    const float* W3 = (const float*)d_in[5];
    const float* b3 = (const float*)d_in[6];
    const float* Wl = (const float*)d_in[7];
    const float* bl = (const float*)d_in[8];
    const int* ei    = (const int*)d_in[9];
    const int* batch = (const int*)d_in[10];
    float* out = (float*)d_out;

    __half *p_w1h, *p_w2h, *p_w3h, *p_h1, *p_x2, *p_h2, *p_x3, *p_h3;
    cudaGetSymbolAddress((void**)&p_w1h, g_w1h);
    cudaGetSymbolAddress((void**)&p_w2h, g_w2h);
    cudaGetSymbolAddress((void**)&p_w3h, g_w3h);
    cudaGetSymbolAddress((void**)&p_h1,  g_h1);
    cudaGetSymbolAddress((void**)&p_x2,  g_x2);
    cudaGetSymbolAddress((void**)&p_h2,  g_h2);
    cudaGetSymbolAddress((void**)&p_x3,  g_x3);
    cudaGetSymbolAddress((void**)&p_h3,  g_h3);

    // smem: (MT*(K+8) + K*(N+8)) * 2 bytes
    int s1 = (128 * 136 + 128 * 136) * 2;   // 69632
    int s2 = (128 * 136 + 128 * 72) * 2;    // 53248
    int s3 = (128 * 72 + 64 * 40) * 2;      // 23552
    cudaFuncSetAttribute(k_l1, cudaFuncAttributeMaxDynamicSharedMemorySize, s1);
    cudaFuncSetAttribute(k_hgemm<128, 64, 8, 2, 512, __half, __half>,
                         cudaFuncAttributeMaxDynamicSharedMemorySize, s2);
    cudaFuncSetAttribute(k_hgemm<64, 32, 8, 1, 256, __half, __half>,
                         cudaFuncAttributeMaxDynamicSharedMemorySize, s3);

    int mblocks = (N_NODES + 127) / 128;    // 313

    // ---- prep (W fp16 convert folded into k_zero) ----
    k_zero <<<NB, 256>>>(W1, W2, W3);
    k_count<<<625, 256>>>(ei, batch);
    k_scan <<<NB, 256>>>();

    // ---- layer 1: gemm1 + CSR fill merged (launch #4, profiled) ----
    k_l1<<<GEMM1_BLOCKS + FILL_BLOCKS, 512, s1>>>(x, p_w1h, p_h1, ei);
    k_agg<128, false><<<2500, 256>>>(p_h1, b1, batch, p_x2);

    // ---- layer 2: 128 -> 64 ----
    k_hgemm<128, 64, 8, 2, 512, __half, __half><<<mblocks, 512, s2>>>(p_x2, p_w2h, p_h2);
    k_agg<64, false><<<1250, 256>>>(p_h2, b2, batch, p_x3);

    // ---- layer 3: 64 -> 32 (pool fused) ----
    k_hgemm<64, 32, 8, 1, 256, __half, __half><<<mblocks, 256, s3>>>(p_x3, p_w3h, p_h3);
    k_agg<32, true><<<625, 256>>>(p_h3, b3, batch, nullptr);

    // ---- head ----
    k_final<<<N_GRAPHS, 256>>>(Wl, bl, out);
}